// round 1
// baseline (speedup 1.0000x reference)
#include <cuda_runtime.h>
#include <cuda_bf16.h>
#include <cstdint>
#include <cstddef>

// Problem dims
#define BB  128
#define SS  256
#define DD  64
#define HH  512
#define H2V 1024
#define GEV 2048
#define GDV 4096
#define TT  60
#define BSV (BB*SS)      // 32768
#define BHV (BB*HH)      // 65536
#define BH2 (BB*H2V)     // 131072

// ---------------- scratch (device globals; no allocation allowed) -------------
__device__ float g_xg  [2*BSV*GEV];   // per-layer gate preactivations [dir][b][s][g] (536MB, reused L0/L1)
__device__ float g_h0  [BSV*H2V];     // encoder layer0 output [b][s][h2]
__device__ float g_enc [BSV*H2V];     // encoder layer1 output [b][s][h2]
__device__ float g_keys[3*BSV*H2V];   // attention keys [i][b][s][h2]
__device__ float g_ehbuf[4*BHV];      // enc h ping-pong [parity][dir][b][h]
__device__ float g_ec   [2*BHV];      // enc c [dir][b][h]
__device__ float g_dh   [6*BH2];      // dec h ping-pong [cell][parity][b][h2]
__device__ float g_dc   [3*BH2];      // dec c [cell][b][h2]
__device__ float g_ctx  [BH2];        // attention context [b][h2]
__device__ float g_prev [BB*DD];      // y_{t-1} [b][d]

__device__ __forceinline__ float sigf(float x) { return 1.0f / (1.0f + expf(-x)); }

// ---------------- generic NT SGEMM: C[M,N] = A[M,K] @ W[N,K]^T + bias[n] ------
// 128x128 tile, 256 threads, 8x8 microtile, K-step 8. M,N multiples of 128; K of 8.
__global__ __launch_bounds__(256) void sgemm_nt(
    const float* __restrict__ A, const float* __restrict__ W,
    const float* __restrict__ bias, float* __restrict__ C,
    int M, int N, int K)
{
    __shared__ float As[8][128];
    __shared__ float Ws[8][128];
    const int tid = threadIdx.x;
    const int bm = blockIdx.y * 128, bn = blockIdx.x * 128;
    const int lr = tid >> 1;            // 0..127 row within tile
    const int lk = (tid & 1) * 4;       // 0 or 4
    const int tx = tid & 15, ty = tid >> 4;

    float acc[8][8];
#pragma unroll
    for (int i = 0; i < 8; i++)
#pragma unroll
        for (int j = 0; j < 8; j++) acc[i][j] = 0.0f;

    for (int k0 = 0; k0 < K; k0 += 8) {
        float4 av = *(const float4*)&A[(long)(bm + lr) * K + k0 + lk];
        float4 wv = *(const float4*)&W[(long)(bn + lr) * K + k0 + lk];
        As[lk + 0][lr] = av.x; As[lk + 1][lr] = av.y; As[lk + 2][lr] = av.z; As[lk + 3][lr] = av.w;
        Ws[lk + 0][lr] = wv.x; Ws[lk + 1][lr] = wv.y; Ws[lk + 2][lr] = wv.z; Ws[lk + 3][lr] = wv.w;
        __syncthreads();
#pragma unroll
        for (int kk = 0; kk < 8; kk++) {
            float a[8], b[8];
            float4 a0 = *(const float4*)&As[kk][ty * 8];
            float4 a1 = *(const float4*)&As[kk][ty * 8 + 4];
            float4 b0 = *(const float4*)&Ws[kk][tx * 8];
            float4 b1 = *(const float4*)&Ws[kk][tx * 8 + 4];
            a[0]=a0.x; a[1]=a0.y; a[2]=a0.z; a[3]=a0.w; a[4]=a1.x; a[5]=a1.y; a[6]=a1.z; a[7]=a1.w;
            b[0]=b0.x; b[1]=b0.y; b[2]=b0.z; b[3]=b0.w; b[4]=b1.x; b[5]=b1.y; b[6]=b1.z; b[7]=b1.w;
#pragma unroll
            for (int i = 0; i < 8; i++)
#pragma unroll
                for (int j = 0; j < 8; j++) acc[i][j] += a[i] * b[j];
        }
        __syncthreads();
    }
#pragma unroll
    for (int i = 0; i < 8; i++) {
        long row = (long)(bm + ty * 8 + i) * N + bn + tx * 8;
        float4 c0, c1;
        c0.x = acc[i][0] + bias[bn + tx*8 + 0]; c0.y = acc[i][1] + bias[bn + tx*8 + 1];
        c0.z = acc[i][2] + bias[bn + tx*8 + 2]; c0.w = acc[i][3] + bias[bn + tx*8 + 3];
        c1.x = acc[i][4] + bias[bn + tx*8 + 4]; c1.y = acc[i][5] + bias[bn + tx*8 + 5];
        c1.z = acc[i][6] + bias[bn + tx*8 + 6]; c1.w = acc[i][7] + bias[bn + tx*8 + 7];
        *(float4*)&C[row]     = c0;
        *(float4*)&C[row + 4] = c1;
    }
}

// ---------------- fused block GEMM segment for LSTM steps ---------------------
// Accumulates acc[gate][bi] += sum_k A[b][k] * W[gate*gstride + base + j][k]
// Block: 256 threads; thread (bq=tid>>3, j=tid&7) owns b in {4bq..4bq+3}, unit j.
__device__ __forceinline__ void gemm_seg(
    float (&acc)[4][4],
    const float* __restrict__ A, int lda,
    const float* __restrict__ W, int ldw, int gstride,
    int Kseg, int base, int tid,
    float (*hsm)[128], float (*wsm)[36])
{
    const int j  = tid & 7;
    const int b0 = (tid >> 3) << 2;
    for (int kc = 0; kc < Kseg; kc += 32) {
        // stage A chunk: h[k][b] for k in [kc,kc+32), all 128 b
        {
            const int bl = tid >> 1, ks = (tid & 1) * 16;
            const float* hr = A + (size_t)bl * lda + kc + ks;
#pragma unroll
            for (int q = 0; q < 16; q += 4) {
                float4 v = *(const float4*)(hr + q);
                hsm[ks + q + 0][bl] = v.x; hsm[ks + q + 1][bl] = v.y;
                hsm[ks + q + 2][bl] = v.z; hsm[ks + q + 3][bl] = v.w;
            }
        }
        // stage W chunk: 32 rows (4 gates x 8 units) x 32 k
        {
            const int r = tid >> 3, k4 = (tid & 7) * 4;
            const int g = r >> 3, jj = r & 7;
            float4 wv = *(const float4*)&W[(size_t)(g * gstride + base + jj) * ldw + kc + k4];
            *(float4*)&wsm[r][k4] = wv;
        }
        __syncthreads();
#pragma unroll
        for (int k = 0; k < 32; k++) {
            float4 hv = *(const float4*)&hsm[k][b0];
            float w0 = wsm[0 * 8 + j][k], w1 = wsm[1 * 8 + j][k];
            float w2 = wsm[2 * 8 + j][k], w3 = wsm[3 * 8 + j][k];
            acc[0][0] += w0 * hv.x; acc[0][1] += w0 * hv.y; acc[0][2] += w0 * hv.z; acc[0][3] += w0 * hv.w;
            acc[1][0] += w1 * hv.x; acc[1][1] += w1 * hv.y; acc[1][2] += w1 * hv.z; acc[1][3] += w1 * hv.w;
            acc[2][0] += w2 * hv.x; acc[2][1] += w2 * hv.y; acc[2][2] += w2 * hv.z; acc[2][3] += w2 * hv.w;
            acc[3][0] += w3 * hv.x; acc[3][1] += w3 * hv.y; acc[3][2] += w3 * hv.z; acc[3][3] += w3 * hv.w;
        }
        __syncthreads();
    }
}

// ---------------- encoder recurrent step (both directions, fused gates) -------
__global__ __launch_bounds__(256) void enc_step(
    const float* __restrict__ xg,   // [2][B*S*GE]
    const float* __restrict__ Whh,  // [2][GE*HH]
    const float* __restrict__ h_in, // [2][B*HH]
    float* __restrict__ h_out,      // [2][B*HH]
    float* __restrict__ cst,        // [2][B*HH]
    float* __restrict__ hs,         // [B][S][H2]
    int t)
{
    __shared__ float hsm[32][128];
    __shared__ float wsm[32][36];
    const int dir = blockIdx.y;
    const int td  = dir ? (SS - 1 - t) : t;
    const int base = blockIdx.x * 8;
    const int tid = threadIdx.x;
    const int j = tid & 7;
    const int b0 = (tid >> 3) << 2;

    const float* xgp = xg + (size_t)dir * BSV * GEV;
    const float* Wp  = Whh + (size_t)dir * GEV * HH;
    const float* hip = h_in + (size_t)dir * BHV;
    float* hop = h_out + (size_t)dir * BHV;
    float* cp  = cst   + (size_t)dir * BHV;

    float acc[4][4];
#pragma unroll
    for (int g = 0; g < 4; g++)
#pragma unroll
        for (int bi = 0; bi < 4; bi++)
            acc[g][bi] = xgp[((size_t)(b0 + bi) * SS + td) * GEV + g * HH + base + j];

    gemm_seg(acc, hip, HH, Wp, HH, HH, HH, base, tid, hsm, wsm);

#pragma unroll
    for (int bi = 0; bi < 4; bi++) {
        const int b = b0 + bi;
        const int hidx = b * HH + base + j;
        float c = sigf(acc[1][bi]) * cp[hidx] + sigf(acc[0][bi]) * tanhf(acc[2][bi]);
        float h = sigf(acc[3][bi]) * tanhf(c);
        cp[hidx]  = c;
        hop[hidx] = h;
        hs[((size_t)b * SS + td) * H2V + dir * HH + base + j] = h;
    }
}

// ---------------- decoder cell: gates = [ctx,inB]@Wih^T + h@Whh^T + b ---------
__global__ __launch_bounds__(256) void dec_cell(
    const float* __restrict__ ctx,   // [B][H2]
    const float* __restrict__ inB,   // [B][KB]
    int KB,
    const float* __restrict__ Wih,   // [GD][H2+KB]
    const float* __restrict__ Whh,   // [GD][H2]
    const float* __restrict__ bias,  // [GD]
    const float* __restrict__ h_in,  // [B][H2]
    float* __restrict__ h_out,       // [B][H2]
    float* __restrict__ cst)         // [B][H2]
{
    __shared__ float hsm[32][128];
    __shared__ float wsm[32][36];
    const int base = blockIdx.x * 8;
    const int tid = threadIdx.x;
    const int j = tid & 7;
    const int b0 = (tid >> 3) << 2;

    float acc[4][4];
#pragma unroll
    for (int g = 0; g < 4; g++) {
        float bv = bias[g * H2V + base + j];
#pragma unroll
        for (int bi = 0; bi < 4; bi++) acc[g][bi] = bv;
    }

    const int ldih = H2V + KB;
    gemm_seg(acc, ctx,  H2V, Wih,        ldih, H2V, H2V, base, tid, hsm, wsm);
    gemm_seg(acc, inB,  KB,  Wih + H2V,  ldih, H2V, KB,  base, tid, hsm, wsm);
    gemm_seg(acc, h_in, H2V, Whh,        H2V,  H2V, H2V, base, tid, hsm, wsm);

#pragma unroll
    for (int bi = 0; bi < 4; bi++) {
        const int b = b0 + bi;
        const int hidx = b * H2V + base + j;
        float c = sigf(acc[1][bi]) * cst[hidx] + sigf(acc[0][bi]) * tanhf(acc[2][bi]);
        float h = sigf(acc[3][bi]) * tanhf(c);
        cst[hidx]  = c;
        h_out[hidx] = h;
    }
}

// ---------------- attention: ctx[b] = softmax(h[b]·keys[b,s]) @ enc[b] --------
__global__ __launch_bounds__(256) void attend(
    const float* __restrict__ h,    // [B][H2]
    const float* __restrict__ keys, // [B][S][H2]
    const float* __restrict__ enc,  // [B][S][H2]
    float* __restrict__ ctx)        // [B][H2]
{
    const int b = blockIdx.x, tid = threadIdx.x;
    __shared__ float sh[H2V];
    __shared__ float sa[SS];
    __shared__ float red[256];

    *(float4*)&sh[tid * 4] = *(const float4*)&h[(size_t)b * H2V + tid * 4];
    __syncthreads();

    // score for s = tid
    const float* kr = keys + ((size_t)b * SS + tid) * H2V;
    float acc = 0.0f;
    for (int k = 0; k < H2V; k += 4) {
        float4 kv = *(const float4*)(kr + k);
        acc += kv.x * sh[k] + kv.y * sh[k + 1] + kv.z * sh[k + 2] + kv.w * sh[k + 3];
    }
    // max-reduce
    red[tid] = acc; __syncthreads();
    for (int off = 128; off; off >>= 1) {
        if (tid < off) red[tid] = fmaxf(red[tid], red[tid + off]);
        __syncthreads();
    }
    float mx = red[0]; __syncthreads();
    float e = expf(acc - mx);
    red[tid] = e; __syncthreads();
    for (int off = 128; off; off >>= 1) {
        if (tid < off) red[tid] += red[tid + off];
        __syncthreads();
    }
    float inv = 1.0f / red[0];
    sa[tid] = e * inv;
    __syncthreads();

    // weighted sum over enc rows; thread owns 4 consecutive dims
    float4 a4 = {0.f, 0.f, 0.f, 0.f};
    const float* er = enc + (size_t)b * SS * H2V + tid * 4;
    for (int s = 0; s < SS; s++) {
        float av = sa[s];
        float4 ev = *(const float4*)(er + (size_t)s * H2V);
        a4.x += av * ev.x; a4.y += av * ev.y; a4.z += av * ev.z; a4.w += av * ev.w;
    }
    *(float4*)&ctx[(size_t)b * H2V + tid * 4] = a4;
}

// ---------------- output projection + feedback ---------------------------------
__global__ __launch_bounds__(64) void out_proj(
    const float* __restrict__ h,   // [B][H2]
    const float* __restrict__ W,   // [D][H2]
    const float* __restrict__ bias,
    float* __restrict__ y,         // [B][T][D]
    float* __restrict__ prev,      // [B][D]
    int t)
{
    const int b = blockIdx.x, d = threadIdx.x;
    __shared__ float sh[H2V];
    for (int i = d; i < H2V; i += 64) sh[i] = h[(size_t)b * H2V + i];
    __syncthreads();
    float acc = bias[d];
    const float* wr = W + (size_t)d * H2V;
    for (int k = 0; k < H2V; k += 4) {
        float4 wv = *(const float4*)(wr + k);
        acc += wv.x * sh[k] + wv.y * sh[k + 1] + wv.z * sh[k + 2] + wv.w * sh[k + 3];
    }
    y[((size_t)b * TT + t) * DD + d] = acc;
    prev[b * DD + d] = acc;
}

__global__ void set_prev(const float* __restrict__ x, float* __restrict__ prev)
{
    int i = blockIdx.x * blockDim.x + threadIdx.x;  // B*D = 8192
    if (i < BB * DD) {
        int b = i / DD, d = i % DD;
        prev[i] = x[((size_t)b * SS + (SS - 1)) * DD + d];
    }
}

// ---------------- host orchestration ------------------------------------------
extern "C" void kernel_launch(void* const* d_in, const int* in_sizes, int n_in,
                              void* d_out, int out_size)
{
    (void)in_sizes; (void)n_in; (void)out_size;
    const float* x        = (const float*)d_in[0];
    const float* enc0_Wih = (const float*)d_in[1];
    const float* enc0_Whh = (const float*)d_in[2];
    const float* enc0_b   = (const float*)d_in[3];
    const float* enc1_Wih = (const float*)d_in[4];
    const float* enc1_Whh = (const float*)d_in[5];
    const float* enc1_b   = (const float*)d_in[6];
    const float* attnW[3] = {(const float*)d_in[7],  (const float*)d_in[9],  (const float*)d_in[11]};
    const float* attnb[3] = {(const float*)d_in[8],  (const float*)d_in[10], (const float*)d_in[12]};
    const float* dec1_Wih = (const float*)d_in[13];
    const float* dec1_Whh = (const float*)d_in[14];
    const float* dec1_b   = (const float*)d_in[15];
    const float* dec2_Wih = (const float*)d_in[16];
    const float* dec2_Whh = (const float*)d_in[17];
    const float* dec2_b   = (const float*)d_in[18];
    const float* dec3_Wih = (const float*)d_in[19];
    const float* dec3_Whh = (const float*)d_in[20];
    const float* dec3_b   = (const float*)d_in[21];
    const float* out_W    = (const float*)d_in[22];
    const float* out_b    = (const float*)d_in[23];
    float* out = (float*)d_out;

    float *xg, *h0, *enc, *keys, *ehbuf, *ec, *dh, *dcst, *ctx, *prev;
    cudaGetSymbolAddress((void**)&xg,    g_xg);
    cudaGetSymbolAddress((void**)&h0,    g_h0);
    cudaGetSymbolAddress((void**)&enc,   g_enc);
    cudaGetSymbolAddress((void**)&keys,  g_keys);
    cudaGetSymbolAddress((void**)&ehbuf, g_ehbuf);
    cudaGetSymbolAddress((void**)&ec,    g_ec);
    cudaGetSymbolAddress((void**)&dh,    g_dh);
    cudaGetSymbolAddress((void**)&dcst,  g_dc);
    cudaGetSymbolAddress((void**)&ctx,   g_ctx);
    cudaGetSymbolAddress((void**)&prev,  g_prev);

    const size_t dirXG = (size_t)BSV * GEV;
    const dim3 gemm_blk(256);

    // ---- encoder layer 0 ----
    cudaMemsetAsync(ehbuf, 0, sizeof(float) * 4 * BHV);
    cudaMemsetAsync(ec,    0, sizeof(float) * 2 * BHV);
    sgemm_nt<<<dim3(GEV / 128, BSV / 128), gemm_blk>>>(x, enc0_Wih,             enc0_b,       xg,         BSV, GEV, DD);
    sgemm_nt<<<dim3(GEV / 128, BSV / 128), gemm_blk>>>(x, enc0_Wih + GEV * DD,  enc0_b + GEV, xg + dirXG, BSV, GEV, DD);
    for (int t = 0; t < SS; t++) {
        int par = t & 1;
        enc_step<<<dim3(HH / 8, 2), 256>>>(xg, enc0_Whh,
                                           ehbuf + (size_t)par * 2 * BHV,
                                           ehbuf + (size_t)(par ^ 1) * 2 * BHV,
                                           ec, h0, t);
    }

    // ---- encoder layer 1 ----
    cudaMemsetAsync(ehbuf, 0, sizeof(float) * 4 * BHV);
    cudaMemsetAsync(ec,    0, sizeof(float) * 2 * BHV);
    sgemm_nt<<<dim3(GEV / 128, BSV / 128), gemm_blk>>>(h0, enc1_Wih,                 enc1_b,       xg,         BSV, GEV, H2V);
    sgemm_nt<<<dim3(GEV / 128, BSV / 128), gemm_blk>>>(h0, enc1_Wih + GEV * H2V,     enc1_b + GEV, xg + dirXG, BSV, GEV, H2V);
    for (int t = 0; t < SS; t++) {
        int par = t & 1;
        enc_step<<<dim3(HH / 8, 2), 256>>>(xg, enc1_Whh,
                                           ehbuf + (size_t)par * 2 * BHV,
                                           ehbuf + (size_t)(par ^ 1) * 2 * BHV,
                                           ec, enc, t);
    }

    // ---- keys ----
    for (int i = 0; i < 3; i++)
        sgemm_nt<<<dim3(H2V / 128, BSV / 128), gemm_blk>>>(enc, attnW[i], attnb[i],
                                                           keys + (size_t)i * BSV * H2V, BSV, H2V, H2V);

    // ---- decoder init ----
    cudaMemsetAsync(dh,   0, sizeof(float) * 6 * BH2);
    cudaMemsetAsync(dcst, 0, sizeof(float) * 3 * BH2);
    set_prev<<<32, 256>>>(x, prev);

    // ---- decoder loop ----
    const size_t cs = (size_t)2 * BH2;
    for (int t = 0; t < TT; t++) {
        int par = t & 1;
        float* h1i = dh + 0 * cs + (size_t)par * BH2;
        float* h1o = dh + 0 * cs + (size_t)(par ^ 1) * BH2;
        float* h2i = dh + 1 * cs + (size_t)par * BH2;
        float* h2o = dh + 1 * cs + (size_t)(par ^ 1) * BH2;
        float* h3i = dh + 2 * cs + (size_t)par * BH2;
        float* h3o = dh + 2 * cs + (size_t)(par ^ 1) * BH2;

        attend<<<BB, 256>>>(h1i, keys,                         enc, ctx);
        dec_cell<<<H2V / 8, 256>>>(ctx, prev, DD,  dec1_Wih, dec1_Whh, dec1_b, h1i, h1o, dcst + 0 * BH2);

        attend<<<BB, 256>>>(h2i, keys + (size_t)BSV * H2V,     enc, ctx);
        dec_cell<<<H2V / 8, 256>>>(ctx, h1o,  H2V, dec2_Wih, dec2_Whh, dec2_b, h2i, h2o, dcst + 1 * BH2);

        attend<<<BB, 256>>>(h3i, keys + (size_t)2 * BSV * H2V, enc, ctx);
        dec_cell<<<H2V / 8, 256>>>(ctx, h2o,  H2V, dec3_Wih, dec3_Whh, dec3_b, h3i, h3o, dcst + 2 * BH2);

        out_proj<<<BB, 64>>>(h3o, out_W, out_b, out, prev, t);
    }
}

// round 5
// speedup vs baseline: 1.2345x; 1.2345x over previous
#include <cuda_runtime.h>
#include <cuda_bf16.h>
#include <cstdint>
#include <cstddef>

// Problem dims
#define BB  128
#define SS  256
#define DD  64
#define HH  512
#define H2V 1024
#define GEV 2048
#define GDV 4096
#define TT  60
#define BSV (BB*SS)      // 32768
#define BHV (BB*HH)      // 65536
#define BH2 (BB*H2V)     // 131072

// ---------------- scratch (device globals; no allocation allowed) -------------
__device__ float g_xg  [2*BSV*GEV];   // per-layer gate preactivations [dir][b][s][g]
__device__ float g_h0  [BSV*H2V];     // encoder layer0 output [b][s][h2]
__device__ float g_enc [BSV*H2V];     // encoder layer1 output [b][s][h2]
__device__ float g_keys[3*BSV*H2V];   // attention keys [i][b][s][h2]
__device__ float g_ehbuf[4*BHV];      // enc h ping-pong [parity][dir][b][h]
__device__ float g_ec   [2*BHV];      // enc c [dir][b][h]
__device__ float g_dh   [6*BH2];      // dec h ping-pong [cell][parity][b][h2]
__device__ float g_dc   [3*BH2];      // dec c [cell][b][h2]
__device__ float g_ctx  [3*BH2];      // attention contexts [head][b][h2]
__device__ float g_prev [BB*DD];      // y_{t-1} [b][d]

// bf16 split buffers for tensor-core GEMMs
__device__ __nv_bfloat16 g_abf_hi[BSV*H2V];
__device__ __nv_bfloat16 g_abf_lo[BSV*H2V];
__device__ __nv_bfloat16 g_wbf_hi[2*GEV*H2V];
__device__ __nv_bfloat16 g_wbf_lo[2*GEV*H2V];

__device__ __forceinline__ float sigf(float x) { return 1.0f / (1.0f + expf(-x)); }

__device__ __forceinline__ uint32_t smem_u32(const void* p) {
    uint32_t a;
    asm("{ .reg .u64 t; cvta.to.shared.u64 t, %1; cvt.u32.u64 %0, t; }" : "=r"(a) : "l"(p));
    return a;
}

// =====================  HMMA bf16-split GEMM (mma.sync) ======================
// C[M,N] = A[M,K] @ W[N,K]^T + bias[n]; fp32 via bf16 hi/lo split (3 MMAs).
// Block tile 128x128, 8 warps of 32x64, K-chunk 32, 2-stage cp.async.
// NT layout: BOTH operands stored [rows][K] -> both use NON-trans ldmatrix.

#define MMA4(d, a, b0v, b1v) \
    asm volatile( \
        "mma.sync.aligned.m16n8k16.row.col.f32.bf16.bf16.f32 " \
        "{%0,%1,%2,%3},{%4,%5,%6,%7},{%8,%9},{%0,%1,%2,%3};" \
        : "+f"((d)[0]), "+f"((d)[1]), "+f"((d)[2]), "+f"((d)[3]) \
        : "r"((a)[0]), "r"((a)[1]), "r"((a)[2]), "r"((a)[3]), "r"(b0v), "r"(b1v))

#define LDSM4(r, addr) \
    asm volatile("ldmatrix.sync.aligned.m8n8.x4.shared.b16 {%0,%1,%2,%3},[%4];" \
        : "=r"((r)[0]), "=r"((r)[1]), "=r"((r)[2]), "=r"((r)[3]) : "r"(addr))

#define LDSM4B(r0, r1, r2, r3, addr) \
    asm volatile("ldmatrix.sync.aligned.m8n8.x4.shared.b16 {%0,%1,%2,%3},[%4];" \
        : "=r"(r0), "=r"(r1), "=r"(r2), "=r"(r3) : "r"(addr))

#define G_TILE_B 10240           // 128 rows * 80B (32 bf16 + 16B pad)
#define G_STG    (4 * G_TILE_B)  // Ah, Al, Wh, Wl
#define G_DSM    (2 * G_STG + 128)

__global__ __launch_bounds__(256) void gemm_mma(
    const __nv_bfloat16* __restrict__ Ahi, const __nv_bfloat16* __restrict__ Alo,
    const __nv_bfloat16* __restrict__ Whi, const __nv_bfloat16* __restrict__ Wlo,
    const float* __restrict__ bias, float* __restrict__ C, int N, int K)
{
    extern __shared__ char dsm[];
    const int tid = threadIdx.x, lane = tid & 31, wid = tid >> 5;
    const int wr = wid >> 1, wc = wid & 1;
    const int bn = blockIdx.x * 128, bm = blockIdx.y * 128;
    const uint32_t sbase = (smem_u32(dsm) + 127u) & ~127u;
    const int nch = K >> 5;

    float acc[2][8][4];
#pragma unroll
    for (int mi = 0; mi < 2; mi++)
#pragma unroll
        for (int ni = 0; ni < 8; ni++)
#pragma unroll
            for (int q = 0; q < 4; q++) acc[mi][ni][q] = 0.0f;

    auto load = [&](int c, int st) {
#pragma unroll
        for (int q = 0; q < 8; q++) {
            int id = q * 256 + tid;          // 0..2047
            int t  = id >> 9;                // tile: 0=Ah 1=Al 2=Wh 3=Wl
            int r  = (id >> 2) & 127;        // row in tile
            int sg = id & 3;                 // 16B segment
            const __nv_bfloat16* basep = (t == 0 ? Ahi : t == 1 ? Alo : t == 2 ? Whi : Wlo);
            int grow = (t < 2 ? bm : bn) + r;
            const __nv_bfloat16* src = basep + (size_t)grow * K + c * 32 + sg * 8;
            uint32_t dst = sbase + st * G_STG + t * G_TILE_B + r * 80 + sg * 16;
            asm volatile("cp.async.cg.shared.global [%0], [%1], 16;" :: "r"(dst), "l"(src));
        }
        asm volatile("cp.async.commit_group;" ::: "memory");
    };

    load(0, 0);

    for (int c = 0; c < nch; c++) {
        if (c + 1 < nch) {
            load(c + 1, (c + 1) & 1);
            asm volatile("cp.async.wait_group 1;" ::: "memory");
        } else {
            asm volatile("cp.async.wait_group 0;" ::: "memory");
        }
        __syncthreads();

        const uint32_t stb = sbase + (c & 1) * G_STG;
        const uint32_t aB[2] = { stb, stb + G_TILE_B };
        const uint32_t wB[2] = { stb + 2 * G_TILE_B, stb + 3 * G_TILE_B };
        const int arow = wr * 32 + (lane & 15);
        const int wrow = wc * 64 + (lane & 15);
        const int cc   = (lane >> 4) * 16;   // byte offset within 32-bf16 row

#pragma unroll
        for (int ks = 0; ks < 2; ks++) {
            uint32_t afr[2][2][4];
#pragma unroll
            for (int s = 0; s < 2; s++)
#pragma unroll
                for (int mi = 0; mi < 2; mi++) {
                    uint32_t ad = aB[s] + (uint32_t)(arow + mi * 16) * 80 + ks * 32 + cc;
                    LDSM4(afr[s][mi], ad);
                }
#pragma unroll
            for (int wsp = 0; wsp < 2; wsp++) {
#pragma unroll
                for (int nb = 0; nb < 4; nb++) {
                    uint32_t r0, r1, r2, r3;
                    uint32_t bd = wB[wsp] + (uint32_t)(wrow + nb * 16) * 80 + ks * 32 + cc;
                    // NT layout: non-trans ldmatrix yields correct k-consecutive B frags
                    LDSM4B(r0, r1, r2, r3, bd);
#pragma unroll
                    for (int mi = 0; mi < 2; mi++) {
                        // ntile0 = rows nb*16..+7 -> frag {r0, r2}; ntile1 -> {r1, r3}
                        MMA4(acc[mi][nb * 2],     afr[0][mi], r0, r2);
                        MMA4(acc[mi][nb * 2 + 1], afr[0][mi], r1, r3);
                        if (wsp == 0) {
                            MMA4(acc[mi][nb * 2],     afr[1][mi], r0, r2);
                            MMA4(acc[mi][nb * 2 + 1], afr[1][mi], r1, r3);
                        }
                    }
                }
            }
        }
        __syncthreads();
    }

    // epilogue: D frag lane mapping: d0/d1 at (row=lane>>2, col=(lane&3)*2 {+1}); d2/d3 at row+8
#pragma unroll
    for (int mi = 0; mi < 2; mi++) {
#pragma unroll
        for (int ni = 0; ni < 8; ni++) {
            int r0 = bm + wr * 32 + mi * 16 + (lane >> 2);
            int c0 = bn + wc * 64 + ni * 8 + (lane & 3) * 2;
            float b0v = bias[c0], b1v = bias[c0 + 1];
            float2 v0 = { acc[mi][ni][0] + b0v, acc[mi][ni][1] + b1v };
            float2 v1 = { acc[mi][ni][2] + b0v, acc[mi][ni][3] + b1v };
            *(float2*)&C[(size_t)r0 * N + c0]       = v0;
            *(float2*)&C[(size_t)(r0 + 8) * N + c0] = v1;
        }
    }
}

// fp32 -> bf16 hi/lo split
__global__ void split_bf16(const float* __restrict__ s, __nv_bfloat16* __restrict__ hi,
                           __nv_bfloat16* __restrict__ lo, long n)
{
    long stride = (long)gridDim.x * blockDim.x;
    for (long i = blockIdx.x * (long)blockDim.x + threadIdx.x; i < n; i += stride) {
        float v = s[i];
        __nv_bfloat16 h = __float2bfloat16(v);
        hi[i] = h;
        lo[i] = __float2bfloat16(v - __bfloat162float(h));
    }
}

// ---------------- fused block GEMM segment for LSTM steps ---------------------
__device__ __forceinline__ void gemm_seg(
    float (&acc)[4][4],
    const float* __restrict__ A, int lda,
    const float* __restrict__ W, int ldw, int gstride,
    int Kseg, int base, int tid,
    float (*hsm)[128], float (*wsm)[36])
{
    const int j  = tid & 7;
    const int b0 = (tid >> 3) << 2;
    for (int kc = 0; kc < Kseg; kc += 32) {
        {
            const int bl = tid >> 1, ks = (tid & 1) * 16;
            const float* hr = A + (size_t)bl * lda + kc + ks;
#pragma unroll
            for (int q = 0; q < 16; q += 4) {
                float4 v = *(const float4*)(hr + q);
                hsm[ks + q + 0][bl] = v.x; hsm[ks + q + 1][bl] = v.y;
                hsm[ks + q + 2][bl] = v.z; hsm[ks + q + 3][bl] = v.w;
            }
        }
        {
            const int r = tid >> 3, k4 = (tid & 7) * 4;
            const int g = r >> 3, jj = r & 7;
            float4 wv = *(const float4*)&W[(size_t)(g * gstride + base + jj) * ldw + kc + k4];
            *(float4*)&wsm[r][k4] = wv;
        }
        __syncthreads();
#pragma unroll
        for (int k = 0; k < 32; k++) {
            float4 hv = *(const float4*)&hsm[k][b0];
            float w0 = wsm[0 * 8 + j][k], w1 = wsm[1 * 8 + j][k];
            float w2 = wsm[2 * 8 + j][k], w3 = wsm[3 * 8 + j][k];
            acc[0][0] += w0 * hv.x; acc[0][1] += w0 * hv.y; acc[0][2] += w0 * hv.z; acc[0][3] += w0 * hv.w;
            acc[1][0] += w1 * hv.x; acc[1][1] += w1 * hv.y; acc[1][2] += w1 * hv.z; acc[1][3] += w1 * hv.w;
            acc[2][0] += w2 * hv.x; acc[2][1] += w2 * hv.y; acc[2][2] += w2 * hv.z; acc[2][3] += w2 * hv.w;
            acc[3][0] += w3 * hv.x; acc[3][1] += w3 * hv.y; acc[3][2] += w3 * hv.z; acc[3][3] += w3 * hv.w;
        }
        __syncthreads();
    }
}

// ---------------- encoder recurrent step (both directions, fused gates) -------
__global__ __launch_bounds__(256) void enc_step(
    const float* __restrict__ xg,
    const float* __restrict__ Whh,
    const float* __restrict__ h_in,
    float* __restrict__ h_out,
    float* __restrict__ cst,
    float* __restrict__ hs,
    int t)
{
    __shared__ float hsm[32][128];
    __shared__ float wsm[32][36];
    const int dir = blockIdx.y;
    const int td  = dir ? (SS - 1 - t) : t;
    const int base = blockIdx.x * 8;
    const int tid = threadIdx.x;
    const int j = tid & 7;
    const int b0 = (tid >> 3) << 2;

    const float* xgp = xg + (size_t)dir * BSV * GEV;
    const float* Wp  = Whh + (size_t)dir * GEV * HH;
    const float* hip = h_in + (size_t)dir * BHV;
    float* hop = h_out + (size_t)dir * BHV;
    float* cp  = cst   + (size_t)dir * BHV;

    float acc[4][4];
#pragma unroll
    for (int g = 0; g < 4; g++)
#pragma unroll
        for (int bi = 0; bi < 4; bi++)
            acc[g][bi] = xgp[((size_t)(b0 + bi) * SS + td) * GEV + g * HH + base + j];

    gemm_seg(acc, hip, HH, Wp, HH, HH, HH, base, tid, hsm, wsm);

#pragma unroll
    for (int bi = 0; bi < 4; bi++) {
        const int b = b0 + bi;
        const int hidx = b * HH + base + j;
        float c = sigf(acc[1][bi]) * cp[hidx] + sigf(acc[0][bi]) * tanhf(acc[2][bi]);
        float h = sigf(acc[3][bi]) * tanhf(c);
        cp[hidx]  = c;
        hop[hidx] = h;
        hs[((size_t)b * SS + td) * H2V + dir * HH + base + j] = h;
    }
}

// ---------------- decoder cell ------------------------------------------------
__global__ __launch_bounds__(256) void dec_cell(
    const float* __restrict__ ctx,
    const float* __restrict__ inB,
    int KB,
    const float* __restrict__ Wih,
    const float* __restrict__ Whh,
    const float* __restrict__ bias,
    const float* __restrict__ h_in,
    float* __restrict__ h_out,
    float* __restrict__ cst)
{
    __shared__ float hsm[32][128];
    __shared__ float wsm[32][36];
    const int base = blockIdx.x * 8;
    const int tid = threadIdx.x;
    const int j = tid & 7;
    const int b0 = (tid >> 3) << 2;

    float acc[4][4];
#pragma unroll
    for (int g = 0; g < 4; g++) {
        float bv = bias[g * H2V + base + j];
#pragma unroll
        for (int bi = 0; bi < 4; bi++) acc[g][bi] = bv;
    }

    const int ldih = H2V + KB;
    gemm_seg(acc, ctx,  H2V, Wih,        ldih, H2V, H2V, base, tid, hsm, wsm);
    gemm_seg(acc, inB,  KB,  Wih + H2V,  ldih, H2V, KB,  base, tid, hsm, wsm);
    gemm_seg(acc, h_in, H2V, Whh,        H2V,  H2V, H2V, base, tid, hsm, wsm);

#pragma unroll
    for (int bi = 0; bi < 4; bi++) {
        const int b = b0 + bi;
        const int hidx = b * H2V + base + j;
        float c = sigf(acc[1][bi]) * cst[hidx] + sigf(acc[0][bi]) * tanhf(acc[2][bi]);
        float h = sigf(acc[3][bi]) * tanhf(c);
        cst[hidx]  = c;
        h_out[hidx] = h;
    }
}

// ---------------- attention (all 3 heads in one launch) -----------------------
__global__ __launch_bounds__(256) void attend3(
    const float* __restrict__ hbase,   // h for head i at hbase + i*2*BH2
    const float* __restrict__ keys,    // [head][B][S][H2]
    const float* __restrict__ enc,     // [B][S][H2]
    float* __restrict__ ctx)           // [head][B][H2]
{
    const int b = blockIdx.x, head = blockIdx.y, tid = threadIdx.x;
    const float* h  = hbase + (size_t)head * 2 * BH2;
    const float* kb = keys + (size_t)head * BSV * H2V;
    float* cc = ctx + (size_t)head * BH2;

    __shared__ float sh[H2V];
    __shared__ float sa[SS];
    __shared__ float red[256];

    *(float4*)&sh[tid * 4] = *(const float4*)&h[(size_t)b * H2V + tid * 4];
    __syncthreads();

    const float* kr = kb + ((size_t)b * SS + tid) * H2V;
    float acc = 0.0f;
    for (int k = 0; k < H2V; k += 4) {
        float4 kv = *(const float4*)(kr + k);
        acc += kv.x * sh[k] + kv.y * sh[k + 1] + kv.z * sh[k + 2] + kv.w * sh[k + 3];
    }
    red[tid] = acc; __syncthreads();
    for (int off = 128; off; off >>= 1) {
        if (tid < off) red[tid] = fmaxf(red[tid], red[tid + off]);
        __syncthreads();
    }
    float mx = red[0]; __syncthreads();
    float e = expf(acc - mx);
    red[tid] = e; __syncthreads();
    for (int off = 128; off; off >>= 1) {
        if (tid < off) red[tid] += red[tid + off];
        __syncthreads();
    }
    float inv = 1.0f / red[0];
    sa[tid] = e * inv;
    __syncthreads();

    float4 a4 = {0.f, 0.f, 0.f, 0.f};
    const float* er = enc + (size_t)b * SS * H2V + tid * 4;
    for (int s = 0; s < SS; s++) {
        float av = sa[s];
        float4 ev = *(const float4*)(er + (size_t)s * H2V);
        a4.x += av * ev.x; a4.y += av * ev.y; a4.z += av * ev.z; a4.w += av * ev.w;
    }
    *(float4*)&cc[(size_t)b * H2V + tid * 4] = a4;
}

// ---------------- output projection + feedback --------------------------------
__global__ __launch_bounds__(64) void out_proj(
    const float* __restrict__ h,
    const float* __restrict__ W,
    const float* __restrict__ bias,
    float* __restrict__ y,
    float* __restrict__ prev,
    int t)
{
    const int b = blockIdx.x, d = threadIdx.x;
    __shared__ float sh[H2V];
    for (int i = d; i < H2V; i += 64) sh[i] = h[(size_t)b * H2V + i];
    __syncthreads();
    float acc = bias[d];
    const float* wr = W + (size_t)d * H2V;
    for (int k = 0; k < H2V; k += 4) {
        float4 wv = *(const float4*)(wr + k);
        acc += wv.x * sh[k] + wv.y * sh[k + 1] + wv.z * sh[k + 2] + wv.w * sh[k + 3];
    }
    y[((size_t)b * TT + t) * DD + d] = acc;
    prev[b * DD + d] = acc;
}

__global__ void set_prev(const float* __restrict__ x, float* __restrict__ prev)
{
    int i = blockIdx.x * blockDim.x + threadIdx.x;
    if (i < BB * DD) {
        int b = i / DD, d = i % DD;
        prev[i] = x[((size_t)b * SS + (SS - 1)) * DD + d];
    }
}

// ---------------- host orchestration ------------------------------------------
extern "C" void kernel_launch(void* const* d_in, const int* in_sizes, int n_in,
                              void* d_out, int out_size)
{
    (void)in_sizes; (void)n_in; (void)out_size;
    const float* x        = (const float*)d_in[0];
    const float* enc0_Wih = (const float*)d_in[1];
    const float* enc0_Whh = (const float*)d_in[2];
    const float* enc0_b   = (const float*)d_in[3];
    const float* enc1_Wih = (const float*)d_in[4];
    const float* enc1_Whh = (const float*)d_in[5];
    const float* enc1_b   = (const float*)d_in[6];
    const float* attnW[3] = {(const float*)d_in[7],  (const float*)d_in[9],  (const float*)d_in[11]};
    const float* attnb[3] = {(const float*)d_in[8],  (const float*)d_in[10], (const float*)d_in[12]};
    const float* dec1_Wih = (const float*)d_in[13];
    const float* dec1_Whh = (const float*)d_in[14];
    const float* dec1_b   = (const float*)d_in[15];
    const float* dec2_Wih = (const float*)d_in[16];
    const float* dec2_Whh = (const float*)d_in[17];
    const float* dec2_b   = (const float*)d_in[18];
    const float* dec3_Wih = (const float*)d_in[19];
    const float* dec3_Whh = (const float*)d_in[20];
    const float* dec3_b   = (const float*)d_in[21];
    const float* out_W    = (const float*)d_in[22];
    const float* out_b    = (const float*)d_in[23];
    float* out = (float*)d_out;

    float *xg, *h0, *enc, *keys, *ehbuf, *ec, *dh, *dcst, *ctx, *prev;
    __nv_bfloat16 *ah, *al, *wh, *wl;
    cudaGetSymbolAddress((void**)&xg,    g_xg);
    cudaGetSymbolAddress((void**)&h0,    g_h0);
    cudaGetSymbolAddress((void**)&enc,   g_enc);
    cudaGetSymbolAddress((void**)&keys,  g_keys);
    cudaGetSymbolAddress((void**)&ehbuf, g_ehbuf);
    cudaGetSymbolAddress((void**)&ec,    g_ec);
    cudaGetSymbolAddress((void**)&dh,    g_dh);
    cudaGetSymbolAddress((void**)&dcst,  g_dc);
    cudaGetSymbolAddress((void**)&ctx,   g_ctx);
    cudaGetSymbolAddress((void**)&prev,  g_prev);
    cudaGetSymbolAddress((void**)&ah,    g_abf_hi);
    cudaGetSymbolAddress((void**)&al,    g_abf_lo);
    cudaGetSymbolAddress((void**)&wh,    g_wbf_hi);
    cudaGetSymbolAddress((void**)&wl,    g_wbf_lo);

    cudaFuncSetAttribute(gemm_mma, cudaFuncAttributeMaxDynamicSharedMemorySize, G_DSM);

    const size_t dirXG = (size_t)BSV * GEV;

    // ---- encoder layer 0 ----
    cudaMemsetAsync(ehbuf, 0, sizeof(float) * 4 * BHV);
    cudaMemsetAsync(ec,    0, sizeof(float) * 2 * BHV);
    split_bf16<<<1024, 256>>>(x, ah, al, (long)BSV * DD);
    split_bf16<<<1024, 256>>>(enc0_Wih, wh, wl, 2L * GEV * DD);
    gemm_mma<<<dim3(GEV / 128, BSV / 128), 256, G_DSM>>>(ah, al, wh, wl, enc0_b, xg, GEV, DD);
    gemm_mma<<<dim3(GEV / 128, BSV / 128), 256, G_DSM>>>(ah, al, wh + (size_t)GEV * DD, wl + (size_t)GEV * DD,
                                                         enc0_b + GEV, xg + dirXG, GEV, DD);
    for (int t = 0; t < SS; t++) {
        int par = t & 1;
        enc_step<<<dim3(HH / 8, 2), 256>>>(xg, enc0_Whh,
                                           ehbuf + (size_t)par * 2 * BHV,
                                           ehbuf + (size_t)(par ^ 1) * 2 * BHV,
                                           ec, h0, t);
    }

    // ---- encoder layer 1 ----
    cudaMemsetAsync(ehbuf, 0, sizeof(float) * 4 * BHV);
    cudaMemsetAsync(ec,    0, sizeof(float) * 2 * BHV);
    split_bf16<<<1024, 256>>>(h0, ah, al, (long)BSV * H2V);
    split_bf16<<<1024, 256>>>(enc1_Wih, wh, wl, 2L * GEV * H2V);
    gemm_mma<<<dim3(GEV / 128, BSV / 128), 256, G_DSM>>>(ah, al, wh, wl, enc1_b, xg, GEV, H2V);
    gemm_mma<<<dim3(GEV / 128, BSV / 128), 256, G_DSM>>>(ah, al, wh + (size_t)GEV * H2V, wl + (size_t)GEV * H2V,
                                                         enc1_b + GEV, xg + dirXG, GEV, H2V);
    for (int t = 0; t < SS; t++) {
        int par = t & 1;
        enc_step<<<dim3(HH / 8, 2), 256>>>(xg, enc1_Whh,
                                           ehbuf + (size_t)par * 2 * BHV,
                                           ehbuf + (size_t)(par ^ 1) * 2 * BHV,
                                           ec, enc, t);
    }

    // ---- keys ----
    split_bf16<<<1024, 256>>>(enc, ah, al, (long)BSV * H2V);
    for (int i = 0; i < 3; i++)
        split_bf16<<<1024, 256>>>(attnW[i], wh + (size_t)i * H2V * H2V, wl + (size_t)i * H2V * H2V,
                                  (long)H2V * H2V);
    for (int i = 0; i < 3; i++)
        gemm_mma<<<dim3(H2V / 128, BSV / 128), 256, G_DSM>>>(ah, al,
                                                             wh + (size_t)i * H2V * H2V,
                                                             wl + (size_t)i * H2V * H2V,
                                                             attnb[i], keys + (size_t)i * BSV * H2V,
                                                             H2V, H2V);

    // ---- decoder init ----
    cudaMemsetAsync(dh,   0, sizeof(float) * 6 * BH2);
    cudaMemsetAsync(dcst, 0, sizeof(float) * 3 * BH2);
    set_prev<<<32, 256>>>(x, prev);

    // ---- decoder loop ----
    const size_t cs = (size_t)2 * BH2;
    for (int t = 0; t < TT; t++) {
        int par = t & 1;
        float* h1i = dh + 0 * cs + (size_t)par * BH2;
        float* h1o = dh + 0 * cs + (size_t)(par ^ 1) * BH2;
        float* h2i = dh + 1 * cs + (size_t)par * BH2;
        float* h2o = dh + 1 * cs + (size_t)(par ^ 1) * BH2;
        float* h3i = dh + 2 * cs + (size_t)par * BH2;
        float* h3o = dh + 2 * cs + (size_t)(par ^ 1) * BH2;

        // all 3 contexts depend only on previous-step h's -> one batched launch
        attend3<<<dim3(BB, 3), 256>>>(dh + (size_t)par * BH2, keys, enc, ctx);

        dec_cell<<<H2V / 8, 256>>>(ctx,            prev, DD,  dec1_Wih, dec1_Whh, dec1_b, h1i, h1o, dcst + 0 * BH2);
        dec_cell<<<H2V / 8, 256>>>(ctx + BH2,      h1o,  H2V, dec2_Wih, dec2_Whh, dec2_b, h2i, h2o, dcst + 1 * BH2);
        dec_cell<<<H2V / 8, 256>>>(ctx + 2 * BH2,  h2o,  H2V, dec3_Wih, dec3_Whh, dec3_b, h3i, h3o, dcst + 2 * BH2);

        out_proj<<<BB, 64>>>(h3o, out_W, out_b, out, prev, t);
    }
}

// round 7
// speedup vs baseline: 1.8058x; 1.4628x over previous
#include <cuda_runtime.h>
#include <cuda_bf16.h>
#include <cstdint>
#include <cstddef>

// Problem dims
#define BB  128
#define SS  256
#define DD  64
#define HH  512
#define H2V 1024
#define GEV 2048
#define GDV 4096
#define TT  60
#define BSV (BB*SS)      // 32768
#define BHV (BB*HH)      // 65536
#define BH2 (BB*H2V)     // 131072

// ---------------- scratch (device globals; no allocation allowed) -------------
__device__ float g_xg  [2*BSV*GEV];   // gate preactivations [dir][b][s][g]
__device__ float g_h0  [BSV*H2V];     // encoder layer0 output
__device__ float g_enc [BSV*H2V];     // encoder layer1 output
__device__ float g_keys[3*BSV*H2V];   // attention keys
__device__ float g_ec  [2*BHV];       // enc c [dir][b][h]
__device__ float g_dh  [6*BH2];       // dec h fp32 ping-pong [cell][parity][b][h2]
__device__ float g_dc  [3*BH2];       // dec c

// bf16 split buffers
__device__ __nv_bfloat16 g_abf_hi[BSV*H2V];
__device__ __nv_bfloat16 g_abf_lo[BSV*H2V];
__device__ __nv_bfloat16 g_wbf_hi[2*GEV*H2V];
__device__ __nv_bfloat16 g_wbf_lo[2*GEV*H2V];

// recurrent weights pre-split (hi/lo)
#define OFF_E0   0ull
#define OFF_E1   2097152ull
#define OFF_D1I  4194304ull
#define OFF_D2I  8650752ull
#define OFF_D3I  17039360ull
#define OFF_D1H  25427968ull
#define OFF_D2H  29622272ull
#define OFF_D3H  33816576ull
#define RW_TOT   38010880ull
__device__ __nv_bfloat16 g_rwh[RW_TOT];
__device__ __nv_bfloat16 g_rwl[RW_TOT];

// recurrent activations bf16 hi/lo
__device__ __nv_bfloat16 g_ehbh[2*2*BHV];   // enc h [par][dir][b][512]
__device__ __nv_bfloat16 g_ehbl[2*2*BHV];
__device__ __nv_bfloat16 g_dhbh[3*2*BH2];   // dec h [cell][par][b][1024]
__device__ __nv_bfloat16 g_dhbl[3*2*BH2];
__device__ __nv_bfloat16 g_cxh [3*BH2];     // ctx [head][b][1024]
__device__ __nv_bfloat16 g_cxl [3*BH2];
__device__ __nv_bfloat16 g_pvh [BB*DD];     // prev y bf16
__device__ __nv_bfloat16 g_pvl [BB*DD];

__device__ __forceinline__ float sigf(float x) { return 1.0f / (1.0f + expf(-x)); }

__device__ __forceinline__ uint32_t smem_u32(const void* p) {
    uint32_t a;
    asm("{ .reg .u64 t; cvta.to.shared.u64 t, %1; cvt.u32.u64 %0, t; }" : "=r"(a) : "l"(p));
    return a;
}

#define MMA4(d, a, b0v, b1v) \
    asm volatile( \
        "mma.sync.aligned.m16n8k16.row.col.f32.bf16.bf16.f32 " \
        "{%0,%1,%2,%3},{%4,%5,%6,%7},{%8,%9},{%0,%1,%2,%3};" \
        : "+f"((d)[0]), "+f"((d)[1]), "+f"((d)[2]), "+f"((d)[3]) \
        : "r"((a)[0]), "r"((a)[1]), "r"((a)[2]), "r"((a)[3]), "r"(b0v), "r"(b1v))

#define LDSM4(r, addr) \
    asm volatile("ldmatrix.sync.aligned.m8n8.x4.shared.b16 {%0,%1,%2,%3},[%4];" \
        : "=r"((r)[0]), "=r"((r)[1]), "=r"((r)[2]), "=r"((r)[3]) : "r"(addr))

#define LDSM4B(r0, r1, r2, r3, addr) \
    asm volatile("ldmatrix.sync.aligned.m8n8.x4.shared.b16 {%0,%1,%2,%3},[%4];" \
        : "=r"(r0), "=r"(r1), "=r"(r2), "=r"(r3) : "r"(addr))

// =====================  batch HMMA bf16-split GEMM (verified R5) =============
#define G_TILE_B 10240
#define G_STG    (4 * G_TILE_B)
#define G_DSM    (2 * G_STG + 128)

__global__ __launch_bounds__(256) void gemm_mma(
    const __nv_bfloat16* __restrict__ Ahi, const __nv_bfloat16* __restrict__ Alo,
    const __nv_bfloat16* __restrict__ Whi, const __nv_bfloat16* __restrict__ Wlo,
    const float* __restrict__ bias, float* __restrict__ C, int N, int K)
{
    extern __shared__ char dsm[];
    const int tid = threadIdx.x, lane = tid & 31, wid = tid >> 5;
    const int wr = wid >> 1, wc = wid & 1;
    const int bn = blockIdx.x * 128, bm = blockIdx.y * 128;
    const uint32_t sbase = (smem_u32(dsm) + 127u) & ~127u;
    const int nch = K >> 5;

    float acc[2][8][4];
#pragma unroll
    for (int mi = 0; mi < 2; mi++)
#pragma unroll
        for (int ni = 0; ni < 8; ni++)
#pragma unroll
            for (int q = 0; q < 4; q++) acc[mi][ni][q] = 0.0f;

    auto load = [&](int c, int st) {
#pragma unroll
        for (int q = 0; q < 8; q++) {
            int id = q * 256 + tid;
            int t  = id >> 9;
            int r  = (id >> 2) & 127;
            int sg = id & 3;
            const __nv_bfloat16* basep = (t == 0 ? Ahi : t == 1 ? Alo : t == 2 ? Whi : Wlo);
            int grow = (t < 2 ? bm : bn) + r;
            const __nv_bfloat16* src = basep + (size_t)grow * K + c * 32 + sg * 8;
            uint32_t dst = sbase + st * G_STG + t * G_TILE_B + r * 80 + sg * 16;
            asm volatile("cp.async.cg.shared.global [%0], [%1], 16;" :: "r"(dst), "l"(src));
        }
        asm volatile("cp.async.commit_group;" ::: "memory");
    };

    load(0, 0);

    for (int c = 0; c < nch; c++) {
        if (c + 1 < nch) {
            load(c + 1, (c + 1) & 1);
            asm volatile("cp.async.wait_group 1;" ::: "memory");
        } else {
            asm volatile("cp.async.wait_group 0;" ::: "memory");
        }
        __syncthreads();

        const uint32_t stb = sbase + (c & 1) * G_STG;
        const uint32_t aB[2] = { stb, stb + G_TILE_B };
        const uint32_t wB[2] = { stb + 2 * G_TILE_B, stb + 3 * G_TILE_B };
        const int arow = wr * 32 + (lane & 15);
        const int wrow = wc * 64 + (lane & 15);
        const int cc   = (lane >> 4) * 16;

#pragma unroll
        for (int ks = 0; ks < 2; ks++) {
            uint32_t afr[2][2][4];
#pragma unroll
            for (int s = 0; s < 2; s++)
#pragma unroll
                for (int mi = 0; mi < 2; mi++) {
                    uint32_t ad = aB[s] + (uint32_t)(arow + mi * 16) * 80 + ks * 32 + cc;
                    LDSM4(afr[s][mi], ad);
                }
#pragma unroll
            for (int wsp = 0; wsp < 2; wsp++) {
#pragma unroll
                for (int nb = 0; nb < 4; nb++) {
                    uint32_t r0, r1, r2, r3;
                    uint32_t bd = wB[wsp] + (uint32_t)(wrow + nb * 16) * 80 + ks * 32 + cc;
                    LDSM4B(r0, r1, r2, r3, bd);
#pragma unroll
                    for (int mi = 0; mi < 2; mi++) {
                        MMA4(acc[mi][nb * 2],     afr[0][mi], r0, r2);
                        MMA4(acc[mi][nb * 2 + 1], afr[0][mi], r1, r3);
                        if (wsp == 0) {
                            MMA4(acc[mi][nb * 2],     afr[1][mi], r0, r2);
                            MMA4(acc[mi][nb * 2 + 1], afr[1][mi], r1, r3);
                        }
                    }
                }
            }
        }
        __syncthreads();
    }

#pragma unroll
    for (int mi = 0; mi < 2; mi++) {
#pragma unroll
        for (int ni = 0; ni < 8; ni++) {
            int r0 = bm + wr * 32 + mi * 16 + (lane >> 2);
            int c0 = bn + wc * 64 + ni * 8 + (lane & 3) * 2;
            float b0v = bias[c0], b1v = bias[c0 + 1];
            float2 v0 = { acc[mi][ni][0] + b0v, acc[mi][ni][1] + b1v };
            float2 v1 = { acc[mi][ni][2] + b0v, acc[mi][ni][3] + b1v };
            *(float2*)&C[(size_t)r0 * N + c0]       = v0;
            *(float2*)&C[(size_t)(r0 + 8) * N + c0] = v1;
        }
    }
}

// fp32 -> bf16 hi/lo split
__global__ void split_bf16(const float* __restrict__ s, __nv_bfloat16* __restrict__ hi,
                           __nv_bfloat16* __restrict__ lo, long n)
{
    long stride = (long)gridDim.x * blockDim.x;
    for (long i = blockIdx.x * (long)blockDim.x + threadIdx.x; i < n; i += stride) {
        float v = s[i];
        __nv_bfloat16 h = __float2bfloat16(v);
        hi[i] = h;
        lo[i] = __float2bfloat16(v - __bfloat162float(h));
    }
}

// =====================  HMMA recurrent cell machinery ========================
// Block tile M=128 (batch) x N=32 (4 gates x 8 units); 8 warps of 16x32.
// K chunks of 32, 2-stage cp.async.  smem stage: Ah|Al (128x32) + Wh|Wl (32x32).

#define RC_STG    25600                  // 2*10240 + 2*2560
#define RC_GS_OFF (2 * RC_STG)           // 51200
#define RC_DSM    (RC_GS_OFF + 128 * 34 * 4)   // + 17408 = 68608

struct Seg {
    const __nv_bfloat16 *Ah, *Al, *Wh, *Wl;
    int lda, ldw, nch;
};

__device__ __forceinline__ void rc_load(const Seg& s, int kc, uint32_t stb,
                                        int tid, int ubase, int GST)
{
#pragma unroll
    for (int q = 0; q < 5; q++) {
        int id = q * 256 + tid;      // 0..1279
        uint32_t dst; const __nv_bfloat16* src;
        if (id < 1024) {
            int t = id >> 9, r = (id >> 2) & 127, sg = id & 3;
            src = (t ? s.Al : s.Ah) + (size_t)r * s.lda + kc + sg * 8;
            dst = stb + t * 10240 + r * 80 + sg * 16;
        } else {
            int id2 = id - 1024;     // 0..255 : 2 tiles x 32 rows x 4 segs
            int t = id2 >> 7, r = (id2 >> 2) & 31, sg = id2 & 3;   // FIX: >>7 (was >>8)
            int grow = (r >> 3) * GST + ubase + (r & 7);
            src = (t ? s.Wl : s.Wh) + (size_t)grow * s.ldw + kc + sg * 8;
            dst = stb + 20480 + t * 2560 + r * 80 + sg * 16;
        }
        asm volatile("cp.async.cg.shared.global [%0], [%1], 16;" :: "r"(dst), "l"(src));
    }
    asm volatile("cp.async.commit_group;" ::: "memory");
}

__device__ __forceinline__ void rc_consume(uint32_t stb, int wid, int lane,
                                           float (*acc)[4])
{
    const uint32_t cc   = (lane >> 4) * 16;
    const uint32_t arow = wid * 16 + (lane & 15);
    const uint32_t wrow = (lane & 15);
#pragma unroll
    for (int ks = 0; ks < 2; ks++) {
        uint32_t ah[4], al[4];
        LDSM4(ah, stb + arow * 80 + ks * 32 + cc);
        LDSM4(al, stb + 10240 + arow * 80 + ks * 32 + cc);
        uint32_t b0,b1,b2,b3,b4,b5,b6,b7;
        LDSM4B(b0,b1,b2,b3, stb + 20480 + wrow * 80 + ks * 32 + cc);
        LDSM4B(b4,b5,b6,b7, stb + 20480 + (wrow + 16) * 80 + ks * 32 + cc);
        uint32_t l0,l1,l2,l3,l4,l5,l6,l7;
        LDSM4B(l0,l1,l2,l3, stb + 23040 + wrow * 80 + ks * 32 + cc);
        LDSM4B(l4,l5,l6,l7, stb + 23040 + (wrow + 16) * 80 + ks * 32 + cc);
        MMA4(acc[0], ah, b0, b2); MMA4(acc[0], al, b0, b2); MMA4(acc[0], ah, l0, l2);
        MMA4(acc[1], ah, b1, b3); MMA4(acc[1], al, b1, b3); MMA4(acc[1], ah, l1, l3);
        MMA4(acc[2], ah, b4, b6); MMA4(acc[2], al, b4, b6); MMA4(acc[2], ah, l4, l6);
        MMA4(acc[3], ah, b5, b7); MMA4(acc[3], al, b5, b7); MMA4(acc[3], ah, l5, l7);
    }
}

__device__ __forceinline__ void rc_epilogue_to_smem(float (*gs)[34], float (*acc)[4],
                                                    int wid, int lane)
{
#pragma unroll
    for (int nt = 0; nt < 4; nt++) {
        int r0 = wid * 16 + (lane >> 2);
        int c0 = nt * 8 + (lane & 3) * 2;
        gs[r0][c0]     = acc[nt][0];
        gs[r0][c0 + 1] = acc[nt][1];
        gs[r0 + 8][c0]     = acc[nt][2];
        gs[r0 + 8][c0 + 1] = acc[nt][3];
    }
}

// ---------------- encoder recurrent step (HMMA) -------------------------------
__global__ __launch_bounds__(256) void enc_step_mma(
    const __nv_bfloat16* __restrict__ hh, const __nv_bfloat16* __restrict__ hl, // [dir][B][512]
    const __nv_bfloat16* __restrict__ Wh, const __nv_bfloat16* __restrict__ Wl, // [dir][2048][512]
    const float* __restrict__ xg, float* __restrict__ cst,
    __nv_bfloat16* __restrict__ hho, __nv_bfloat16* __restrict__ hlo,
    float* __restrict__ hs, int t)
{
    extern __shared__ char dsm[];
    const int tid = threadIdx.x, lane = tid & 31, wid = tid >> 5;
    const int dir = blockIdx.y, ubase = blockIdx.x * 8;
    const int td = dir ? (SS - 1 - t) : t;
    const uint32_t sb = smem_u32(dsm);
    float (*gs)[34] = (float (*)[34])(dsm + RC_GS_OFF);

    Seg s = { hh + (size_t)dir * BHV, hl + (size_t)dir * BHV,
              Wh + (size_t)dir * GEV * HH, Wl + (size_t)dir * GEV * HH,
              HH, HH, 16 };

    float acc[4][4];
#pragma unroll
    for (int nt = 0; nt < 4; nt++)
#pragma unroll
        for (int q = 0; q < 4; q++) acc[nt][q] = 0.0f;

    rc_load(s, 0, sb, tid, ubase, HH);
    for (int ci = 0; ci < 16; ci++) {
        if (ci + 1 < 16) {
            rc_load(s, (ci + 1) * 32, sb + ((ci + 1) & 1) * RC_STG, tid, ubase, HH);
            asm volatile("cp.async.wait_group 1;" ::: "memory");
        } else {
            asm volatile("cp.async.wait_group 0;" ::: "memory");
        }
        __syncthreads();
        rc_consume(sb + (ci & 1) * RC_STG, wid, lane, acc);
        __syncthreads();
    }

    rc_epilogue_to_smem(gs, acc, wid, lane);
    __syncthreads();

    const float* xgp = xg + (size_t)dir * BSV * GEV;
    float* cp = cst + (size_t)dir * BHV;
#pragma unroll
    for (int k = 0; k < 4; k++) {
        int idx = k * 256 + tid;
        int b = idx >> 3, u = idx & 7;
        int uu = ubase + u;
        size_t xrow = ((size_t)b * SS + td) * GEV;
        float gi = gs[b][u]      + xgp[xrow + uu];
        float gf = gs[b][8 + u]  + xgp[xrow + 512 + uu];
        float gg = gs[b][16 + u] + xgp[xrow + 1024 + uu];
        float go = gs[b][24 + u] + xgp[xrow + 1536 + uu];
        int hidx = b * HH + uu;
        float c = sigf(gf) * cp[hidx] + sigf(gi) * tanhf(gg);
        float h = sigf(go) * tanhf(c);
        cp[hidx] = c;
        hs[((size_t)b * SS + td) * H2V + dir * HH + uu] = h;
        __nv_bfloat16 hb = __float2bfloat16(h);
        hho[(size_t)dir * BHV + hidx] = hb;
        hlo[(size_t)dir * BHV + hidx] = __float2bfloat16(h - __bfloat162float(hb));
    }
}

// ---------------- decoder cell (HMMA) -----------------------------------------
__global__ __launch_bounds__(256) void dec_cell_mma(
    const __nv_bfloat16* __restrict__ ch, const __nv_bfloat16* __restrict__ cl,  // ctx [B][1024]
    const __nv_bfloat16* __restrict__ ih, const __nv_bfloat16* __restrict__ il, int KB,
    const __nv_bfloat16* __restrict__ hh, const __nv_bfloat16* __restrict__ hl,  // h prev [B][1024]
    const __nv_bfloat16* __restrict__ Wih_h, const __nv_bfloat16* __restrict__ Wih_l, // ldw=H2V+KB
    const __nv_bfloat16* __restrict__ Whh_h, const __nv_bfloat16* __restrict__ Whh_l, // ldw=H2V
    const float* __restrict__ bias, float* __restrict__ cst,
    float* __restrict__ hfo, __nv_bfloat16* __restrict__ hho, __nv_bfloat16* __restrict__ hlo)
{
    extern __shared__ char dsm[];
    const int tid = threadIdx.x, lane = tid & 31, wid = tid >> 5;
    const int ubase = blockIdx.x * 8;
    const uint32_t sb = smem_u32(dsm);
    float (*gs)[34] = (float (*)[34])(dsm + RC_GS_OFF);
    const int ldih = H2V + KB;

    Seg segs[3] = {
        { ch, cl, Wih_h,       Wih_l,       H2V, ldih, 32 },
        { ih, il, Wih_h + H2V, Wih_l + H2V, KB,  ldih, KB >> 5 },
        { hh, hl, Whh_h,       Whh_l,       H2V, H2V,  32 }
    };
    const int total = 64 + (KB >> 5);

    float acc[4][4];
#pragma unroll
    for (int nt = 0; nt < 4; nt++)
#pragma unroll
        for (int q = 0; q < 4; q++) acc[nt][q] = 0.0f;

    int si = 0, kc = 0;
    rc_load(segs[0], 0, sb, tid, ubase, H2V);
    for (int ci = 0; ci < total; ci++) {
        int nsi = si, nkc = kc + 32;
        if (nkc >= segs[nsi].nch * 32) { nsi++; nkc = 0; }
        if (ci + 1 < total) {
            rc_load(segs[nsi], nkc, sb + ((ci + 1) & 1) * RC_STG, tid, ubase, H2V);
            asm volatile("cp.async.wait_group 1;" ::: "memory");
        } else {
            asm volatile("cp.async.wait_group 0;" ::: "memory");
        }
        __syncthreads();
        rc_consume(sb + (ci & 1) * RC_STG, wid, lane, acc);
        __syncthreads();
        si = nsi; kc = nkc;
    }

    rc_epilogue_to_smem(gs, acc, wid, lane);
    __syncthreads();

#pragma unroll
    for (int k = 0; k < 4; k++) {
        int idx = k * 256 + tid;
        int b = idx >> 3, u = idx & 7;
        int uu = ubase + u;
        float gi = gs[b][u]      + bias[uu];
        float gf = gs[b][8 + u]  + bias[1024 + uu];
        float gg = gs[b][16 + u] + bias[2048 + uu];
        float go = gs[b][24 + u] + bias[3072 + uu];
        int hidx = b * H2V + uu;
        float c = sigf(gf) * cst[hidx] + sigf(gi) * tanhf(gg);
        float h = sigf(go) * tanhf(c);
        cst[hidx] = c;
        hfo[hidx] = h;
        __nv_bfloat16 hb = __float2bfloat16(h);
        hho[hidx] = hb;
        hlo[hidx] = __float2bfloat16(h - __bfloat162float(hb));
    }
}

// ---------------- fused 3-head attention --------------------------------------
__global__ __launch_bounds__(256) void attendF(
    const float* __restrict__ dh,      // parity base; head i at dh + i*2*BH2
    const float* __restrict__ keys,    // [head][B][S][H2]
    const float* __restrict__ enc,     // [B][S][H2]
    __nv_bfloat16* __restrict__ cxh, __nv_bfloat16* __restrict__ cxl)  // [head][B][H2]
{
    const int b = blockIdx.x, tid = threadIdx.x;
    __shared__ float sh[3][H2V];
    __shared__ float sa[3][SS];
    __shared__ float red[256];

#pragma unroll
    for (int hd = 0; hd < 3; hd++)
        *(float4*)&sh[hd][tid * 4] =
            *(const float4*)&dh[(size_t)hd * 2 * BH2 + (size_t)b * H2V + tid * 4];
    __syncthreads();

#pragma unroll
    for (int hd = 0; hd < 3; hd++) {
        const float* kr = keys + ((size_t)hd * BSV + (size_t)b * SS + tid) * H2V;
        float acc = 0.0f;
        for (int k = 0; k < H2V; k += 4) {
            float4 kv = *(const float4*)(kr + k);
            acc += kv.x * sh[hd][k] + kv.y * sh[hd][k + 1]
                 + kv.z * sh[hd][k + 2] + kv.w * sh[hd][k + 3];
        }
        red[tid] = acc; __syncthreads();
        for (int off = 128; off; off >>= 1) {
            if (tid < off) red[tid] = fmaxf(red[tid], red[tid + off]);
            __syncthreads();
        }
        float mx = red[0]; __syncthreads();
        float e = expf(acc - mx);
        red[tid] = e; __syncthreads();
        for (int off = 128; off; off >>= 1) {
            if (tid < off) red[tid] += red[tid + off];
            __syncthreads();
        }
        sa[hd][tid] = e / red[0];
        __syncthreads();
    }

    float4 a0 = {0,0,0,0}, a1 = {0,0,0,0}, a2 = {0,0,0,0};
    const float* er = enc + (size_t)b * SS * H2V + tid * 4;
    for (int s = 0; s < SS; s++) {
        float4 ev = *(const float4*)(er + (size_t)s * H2V);
        float w0 = sa[0][s], w1 = sa[1][s], w2 = sa[2][s];
        a0.x += w0 * ev.x; a0.y += w0 * ev.y; a0.z += w0 * ev.z; a0.w += w0 * ev.w;
        a1.x += w1 * ev.x; a1.y += w1 * ev.y; a1.z += w1 * ev.z; a1.w += w1 * ev.w;
        a2.x += w2 * ev.x; a2.y += w2 * ev.y; a2.z += w2 * ev.z; a2.w += w2 * ev.w;
    }
#pragma unroll
    for (int hd = 0; hd < 3; hd++) {
        float4 v = hd == 0 ? a0 : hd == 1 ? a1 : a2;
        size_t base = (size_t)hd * BH2 + (size_t)b * H2V + tid * 4;
        float vv[4] = { v.x, v.y, v.z, v.w };
#pragma unroll
        for (int q = 0; q < 4; q++) {
            __nv_bfloat16 hb = __float2bfloat16(vv[q]);
            cxh[base + q] = hb;
            cxl[base + q] = __float2bfloat16(vv[q] - __bfloat162float(hb));
        }
    }
}

// ---------------- output projection + feedback --------------------------------
__global__ __launch_bounds__(64) void out_proj(
    const float* __restrict__ h,
    const float* __restrict__ W,
    const float* __restrict__ bias,
    float* __restrict__ y,
    __nv_bfloat16* __restrict__ pvh, __nv_bfloat16* __restrict__ pvl,
    int t)
{
    const int b = blockIdx.x, d = threadIdx.x;
    __shared__ float sh[H2V];
    for (int i = d; i < H2V; i += 64) sh[i] = h[(size_t)b * H2V + i];
    __syncthreads();
    float acc = bias[d];
    const float* wr = W + (size_t)d * H2V;
    for (int k = 0; k < H2V; k += 4) {
        float4 wv = *(const float4*)(wr + k);
        acc += wv.x * sh[k] + wv.y * sh[k + 1] + wv.z * sh[k + 2] + wv.w * sh[k + 3];
    }
    y[((size_t)b * TT + t) * DD + d] = acc;
    __nv_bfloat16 hb = __float2bfloat16(acc);
    pvh[b * DD + d] = hb;
    pvl[b * DD + d] = __float2bfloat16(acc - __bfloat162float(hb));
}

__global__ void set_prev(const float* __restrict__ x,
                         __nv_bfloat16* __restrict__ pvh, __nv_bfloat16* __restrict__ pvl)
{
    int i = blockIdx.x * blockDim.x + threadIdx.x;
    if (i < BB * DD) {
        int b = i / DD, d = i % DD;
        float v = x[((size_t)b * SS + (SS - 1)) * DD + d];
        __nv_bfloat16 hb = __float2bfloat16(v);
        pvh[i] = hb;
        pvl[i] = __float2bfloat16(v - __bfloat162float(hb));
    }
}

// ---------------- host orchestration ------------------------------------------
extern "C" void kernel_launch(void* const* d_in, const int* in_sizes, int n_in,
                              void* d_out, int out_size)
{
    (void)in_sizes; (void)n_in; (void)out_size;
    const float* x        = (const float*)d_in[0];
    const float* enc0_Wih = (const float*)d_in[1];
    const float* enc0_Whh = (const float*)d_in[2];
    const float* enc0_b   = (const float*)d_in[3];
    const float* enc1_Wih = (const float*)d_in[4];
    const float* enc1_Whh = (const float*)d_in[5];
    const float* enc1_b   = (const float*)d_in[6];
    const float* attnW[3] = {(const float*)d_in[7],  (const float*)d_in[9],  (const float*)d_in[11]};
    const float* attnb[3] = {(const float*)d_in[8],  (const float*)d_in[10], (const float*)d_in[12]};
    const float* dec1_Wih = (const float*)d_in[13];
    const float* dec1_Whh = (const float*)d_in[14];
    const float* dec1_b   = (const float*)d_in[15];
    const float* dec2_Wih = (const float*)d_in[16];
    const float* dec2_Whh = (const float*)d_in[17];
    const float* dec2_b   = (const float*)d_in[18];
    const float* dec3_Wih = (const float*)d_in[19];
    const float* dec3_Whh = (const float*)d_in[20];
    const float* dec3_b   = (const float*)d_in[21];
    const float* out_W    = (const float*)d_in[22];
    const float* out_b    = (const float*)d_in[23];
    float* out = (float*)d_out;

    float *xg, *h0, *enc, *keys, *ec, *dh, *dcst;
    __nv_bfloat16 *ah, *al, *wh, *wl, *rwh, *rwl;
    __nv_bfloat16 *ehbh, *ehbl, *dhbh, *dhbl, *cxh, *cxl, *pvh, *pvl;
    cudaGetSymbolAddress((void**)&xg,   g_xg);
    cudaGetSymbolAddress((void**)&h0,   g_h0);
    cudaGetSymbolAddress((void**)&enc,  g_enc);
    cudaGetSymbolAddress((void**)&keys, g_keys);
    cudaGetSymbolAddress((void**)&ec,   g_ec);
    cudaGetSymbolAddress((void**)&dh,   g_dh);
    cudaGetSymbolAddress((void**)&dcst, g_dc);
    cudaGetSymbolAddress((void**)&ah,   g_abf_hi);
    cudaGetSymbolAddress((void**)&al,   g_abf_lo);
    cudaGetSymbolAddress((void**)&wh,   g_wbf_hi);
    cudaGetSymbolAddress((void**)&wl,   g_wbf_lo);
    cudaGetSymbolAddress((void**)&rwh,  g_rwh);
    cudaGetSymbolAddress((void**)&rwl,  g_rwl);
    cudaGetSymbolAddress((void**)&ehbh, g_ehbh);
    cudaGetSymbolAddress((void**)&ehbl, g_ehbl);
    cudaGetSymbolAddress((void**)&dhbh, g_dhbh);
    cudaGetSymbolAddress((void**)&dhbl, g_dhbl);
    cudaGetSymbolAddress((void**)&cxh,  g_cxh);
    cudaGetSymbolAddress((void**)&cxl,  g_cxl);
    cudaGetSymbolAddress((void**)&pvh,  g_pvh);
    cudaGetSymbolAddress((void**)&pvl,  g_pvl);

    cudaFuncSetAttribute(gemm_mma,     cudaFuncAttributeMaxDynamicSharedMemorySize, G_DSM);
    cudaFuncSetAttribute(enc_step_mma, cudaFuncAttributeMaxDynamicSharedMemorySize, RC_DSM);
    cudaFuncSetAttribute(dec_cell_mma, cudaFuncAttributeMaxDynamicSharedMemorySize, RC_DSM);

    const size_t dirXG = (size_t)BSV * GEV;

    // ---- pre-split recurrent weights (constant across steps) ----
    split_bf16<<<1024, 256>>>(enc0_Whh, rwh + OFF_E0,  rwl + OFF_E0,  2L * GEV * HH);
    split_bf16<<<1024, 256>>>(enc1_Whh, rwh + OFF_E1,  rwl + OFF_E1,  2L * GEV * HH);
    split_bf16<<<1024, 256>>>(dec1_Wih, rwh + OFF_D1I, rwl + OFF_D1I, (long)GDV * (H2V + DD));
    split_bf16<<<1024, 256>>>(dec2_Wih, rwh + OFF_D2I, rwl + OFF_D2I, (long)GDV * 2 * H2V);
    split_bf16<<<1024, 256>>>(dec3_Wih, rwh + OFF_D3I, rwl + OFF_D3I, (long)GDV * 2 * H2V);
    split_bf16<<<1024, 256>>>(dec1_Whh, rwh + OFF_D1H, rwl + OFF_D1H, (long)GDV * H2V);
    split_bf16<<<1024, 256>>>(dec2_Whh, rwh + OFF_D2H, rwl + OFF_D2H, (long)GDV * H2V);
    split_bf16<<<1024, 256>>>(dec3_Whh, rwh + OFF_D3H, rwl + OFF_D3H, (long)GDV * H2V);

    // ---- encoder layer 0 ----
    cudaMemsetAsync(ehbh, 0, sizeof(__nv_bfloat16) * 2 * 2 * BHV);
    cudaMemsetAsync(ehbl, 0, sizeof(__nv_bfloat16) * 2 * 2 * BHV);
    cudaMemsetAsync(ec,   0, sizeof(float) * 2 * BHV);
    split_bf16<<<1024, 256>>>(x, ah, al, (long)BSV * DD);
    split_bf16<<<1024, 256>>>(enc0_Wih, wh, wl, 2L * GEV * DD);
    gemm_mma<<<dim3(GEV / 128, BSV / 128), 256, G_DSM>>>(ah, al, wh, wl, enc0_b, xg, GEV, DD);
    gemm_mma<<<dim3(GEV / 128, BSV / 128), 256, G_DSM>>>(ah, al, wh + (size_t)GEV * DD, wl + (size_t)GEV * DD,
                                                         enc0_b + GEV, xg + dirXG, GEV, DD);
    const size_t eps = (size_t)2 * BHV;   // encoder parity stride (elems)
    for (int t = 0; t < SS; t++) {
        int par = t & 1;
        enc_step_mma<<<dim3(64, 2), 256, RC_DSM>>>(
            ehbh + par * eps, ehbl + par * eps,
            rwh + OFF_E0, rwl + OFF_E0,
            xg, ec,
            ehbh + (par ^ 1) * eps, ehbl + (par ^ 1) * eps,
            h0, t);
    }

    // ---- encoder layer 1 ----
    cudaMemsetAsync(ehbh, 0, sizeof(__nv_bfloat16) * 2 * 2 * BHV);
    cudaMemsetAsync(ehbl, 0, sizeof(__nv_bfloat16) * 2 * 2 * BHV);
    cudaMemsetAsync(ec,   0, sizeof(float) * 2 * BHV);
    split_bf16<<<1024, 256>>>(h0, ah, al, (long)BSV * H2V);
    split_bf16<<<1024, 256>>>(enc1_Wih, wh, wl, 2L * GEV * H2V);
    gemm_mma<<<dim3(GEV / 128, BSV / 128), 256, G_DSM>>>(ah, al, wh, wl, enc1_b, xg, GEV, H2V);
    gemm_mma<<<dim3(GEV / 128, BSV / 128), 256, G_DSM>>>(ah, al, wh + (size_t)GEV * H2V, wl + (size_t)GEV * H2V,
                                                         enc1_b + GEV, xg + dirXG, GEV, H2V);
    for (int t = 0; t < SS; t++) {
        int par = t & 1;
        enc_step_mma<<<dim3(64, 2), 256, RC_DSM>>>(
            ehbh + par * eps, ehbl + par * eps,
            rwh + OFF_E1, rwl + OFF_E1,
            xg, ec,
            ehbh + (par ^ 1) * eps, ehbl + (par ^ 1) * eps,
            enc, t);
    }

    // ---- keys ----
    split_bf16<<<1024, 256>>>(enc, ah, al, (long)BSV * H2V);
    for (int i = 0; i < 3; i++)
        split_bf16<<<1024, 256>>>(attnW[i], wh + (size_t)i * H2V * H2V, wl + (size_t)i * H2V * H2V,
                                  (long)H2V * H2V);
    for (int i = 0; i < 3; i++)
        gemm_mma<<<dim3(H2V / 128, BSV / 128), 256, G_DSM>>>(ah, al,
                                                             wh + (size_t)i * H2V * H2V,
                                                             wl + (size_t)i * H2V * H2V,
                                                             attnb[i], keys + (size_t)i * BSV * H2V,
                                                             H2V, H2V);

    // ---- decoder init ----
    cudaMemsetAsync(dh,   0, sizeof(float) * 6 * BH2);
    cudaMemsetAsync(dcst, 0, sizeof(float) * 3 * BH2);
    cudaMemsetAsync(dhbh, 0, sizeof(__nv_bfloat16) * 6 * BH2);
    cudaMemsetAsync(dhbl, 0, sizeof(__nv_bfloat16) * 6 * BH2);
    set_prev<<<32, 256>>>(x, pvh, pvl);

    // ---- decoder loop ----
    const size_t cs = (size_t)2 * BH2;   // per-cell stride (fp32 & bf16 mirrors)
    for (int t = 0; t < TT; t++) {
        int par = t & 1;
        attendF<<<BB, 256>>>(dh + (size_t)par * BH2, keys, enc, cxh, cxl);

        // cell 1: inB = prev y (KB=64)
        dec_cell_mma<<<128, 256, RC_DSM>>>(
            cxh, cxl, pvh, pvl, DD,
            dhbh + 0 * cs + (size_t)par * BH2, dhbl + 0 * cs + (size_t)par * BH2,
            rwh + OFF_D1I, rwl + OFF_D1I, rwh + OFF_D1H, rwl + OFF_D1H,
            dec1_b, dcst + 0 * BH2,
            dh + 0 * cs + (size_t)(par ^ 1) * BH2,
            dhbh + 0 * cs + (size_t)(par ^ 1) * BH2, dhbl + 0 * cs + (size_t)(par ^ 1) * BH2);

        // cell 2: inB = h1 (new)
        dec_cell_mma<<<128, 256, RC_DSM>>>(
            cxh + BH2, cxl + BH2,
            dhbh + 0 * cs + (size_t)(par ^ 1) * BH2, dhbl + 0 * cs + (size_t)(par ^ 1) * BH2, H2V,
            dhbh + 1 * cs + (size_t)par * BH2, dhbl + 1 * cs + (size_t)par * BH2,
            rwh + OFF_D2I, rwl + OFF_D2I, rwh + OFF_D2H, rwl + OFF_D2H,
            dec2_b, dcst + 1 * BH2,
            dh + 1 * cs + (size_t)(par ^ 1) * BH2,
            dhbh + 1 * cs + (size_t)(par ^ 1) * BH2, dhbl + 1 * cs + (size_t)(par ^ 1) * BH2);

        // cell 3: inB = h2 (new)
        dec_cell_mma<<<128, 256, RC_DSM>>>(
            cxh + 2 * BH2, cxl + 2 * BH2,
            dhbh + 1 * cs + (size_t)(par ^ 1) * BH2, dhbl + 1 * cs + (size_t)(par ^ 1) * BH2, H2V,
            dhbh + 2 * cs + (size_t)par * BH2, dhbl + 2 * cs + (size_t)par * BH2,
            rwh + OFF_D3I, rwl + OFF_D3I, rwh + OFF_D3H, rwl + OFF_D3H,
            dec3_b, dcst + 2 * BH2,
            dh + 2 * cs + (size_t)(par ^ 1) * BH2,
            dhbh + 2 * cs + (size_t)(par ^ 1) * BH2, dhbl + 2 * cs + (size_t)(par ^ 1) * BH2);

        out_proj<<<BB, 64>>>(dh + 2 * cs + (size_t)(par ^ 1) * BH2, out_W, out_b, out, pvh, pvl, t);
    }
}

// round 8
// speedup vs baseline: 2.2670x; 1.2554x over previous
#include <cuda_runtime.h>
#include <cuda_bf16.h>
#include <cstdint>
#include <cstddef>

// Problem dims
#define BB  128
#define SS  256
#define DD  64
#define HH  512
#define H2V 1024
#define GEV 2048
#define GDV 4096
#define TT  60
#define BSV (BB*SS)      // 32768
#define BHV (BB*HH)      // 65536
#define BH2 (BB*H2V)     // 131072

// ---------------- scratch (device globals; no allocation allowed) -------------
__device__ float g_xg  [2*BSV*GEV];   // gate preactivations [dir][b][s][g]
__device__ float g_h0  [BSV*H2V];     // encoder layer0 output
__device__ float g_enc [BSV*H2V];     // encoder layer1 output
__device__ float g_keys[3*BSV*H2V];   // attention keys
__device__ float g_ec  [2*BHV];       // enc c [dir][b][h]
__device__ float g_dh  [6*BH2];       // dec h fp32 ping-pong [cell][parity][b][h2]
__device__ float g_dc  [3*BH2];       // dec c

// bf16 split buffers
__device__ __nv_bfloat16 g_abf_hi[BSV*H2V];
__device__ __nv_bfloat16 g_abf_lo[BSV*H2V];
__device__ __nv_bfloat16 g_wbf_hi[2*GEV*H2V];
__device__ __nv_bfloat16 g_wbf_lo[2*GEV*H2V];

// recurrent weights pre-split (hi/lo)
#define OFF_E0   0ull
#define OFF_E1   2097152ull
#define OFF_D1I  4194304ull
#define OFF_D2I  8650752ull
#define OFF_D3I  17039360ull
#define OFF_D1H  25427968ull
#define OFF_D2H  29622272ull
#define OFF_D3H  33816576ull
#define RW_TOT   38010880ull
__device__ __nv_bfloat16 g_rwh[RW_TOT];
__device__ __nv_bfloat16 g_rwl[RW_TOT];

// recurrent activations bf16 hi/lo
__device__ __nv_bfloat16 g_ehbh[2*2*BHV];   // enc h [par][dir][b][512]
__device__ __nv_bfloat16 g_ehbl[2*2*BHV];
__device__ __nv_bfloat16 g_dhbh[3*2*BH2];   // dec h [cell][par][b][1024]
__device__ __nv_bfloat16 g_dhbl[3*2*BH2];
__device__ __nv_bfloat16 g_cxh [3*BH2];     // ctx [head][b][1024]
__device__ __nv_bfloat16 g_cxl [3*BH2];
__device__ __nv_bfloat16 g_pvh [BB*DD];     // prev y bf16
__device__ __nv_bfloat16 g_pvl [BB*DD];

__device__ __forceinline__ float sigf(float x) { return 1.0f / (1.0f + expf(-x)); }

__device__ __forceinline__ uint32_t smem_u32(const void* p) {
    uint32_t a;
    asm("{ .reg .u64 t; cvta.to.shared.u64 t, %1; cvt.u32.u64 %0, t; }" : "=r"(a) : "l"(p));
    return a;
}

#define MMA4(d, a, b0v, b1v) \
    asm volatile( \
        "mma.sync.aligned.m16n8k16.row.col.f32.bf16.bf16.f32 " \
        "{%0,%1,%2,%3},{%4,%5,%6,%7},{%8,%9},{%0,%1,%2,%3};" \
        : "+f"((d)[0]), "+f"((d)[1]), "+f"((d)[2]), "+f"((d)[3]) \
        : "r"((a)[0]), "r"((a)[1]), "r"((a)[2]), "r"((a)[3]), "r"(b0v), "r"(b1v))

#define LDSM4(r, addr) \
    asm volatile("ldmatrix.sync.aligned.m8n8.x4.shared.b16 {%0,%1,%2,%3},[%4];" \
        : "=r"((r)[0]), "=r"((r)[1]), "=r"((r)[2]), "=r"((r)[3]) : "r"(addr))

#define LDSM4B(r0, r1, r2, r3, addr) \
    asm volatile("ldmatrix.sync.aligned.m8n8.x4.shared.b16 {%0,%1,%2,%3},[%4];" \
        : "=r"(r0), "=r"(r1), "=r"(r2), "=r"(r3) : "r"(addr))

// =====================  batch HMMA bf16-split GEMM (verified R5) =============
#define G_TILE_B 10240
#define G_STG    (4 * G_TILE_B)
#define G_DSM    (2 * G_STG + 128)

__global__ __launch_bounds__(256) void gemm_mma(
    const __nv_bfloat16* __restrict__ Ahi, const __nv_bfloat16* __restrict__ Alo,
    const __nv_bfloat16* __restrict__ Whi, const __nv_bfloat16* __restrict__ Wlo,
    const float* __restrict__ bias, float* __restrict__ C, int N, int K)
{
    extern __shared__ char dsm[];
    const int tid = threadIdx.x, lane = tid & 31, wid = tid >> 5;
    const int wr = wid >> 1, wc = wid & 1;
    const int bn = blockIdx.x * 128, bm = blockIdx.y * 128;
    const uint32_t sbase = (smem_u32(dsm) + 127u) & ~127u;
    const int nch = K >> 5;

    float acc[2][8][4];
#pragma unroll
    for (int mi = 0; mi < 2; mi++)
#pragma unroll
        for (int ni = 0; ni < 8; ni++)
#pragma unroll
            for (int q = 0; q < 4; q++) acc[mi][ni][q] = 0.0f;

    auto load = [&](int c, int st) {
#pragma unroll
        for (int q = 0; q < 8; q++) {
            int id = q * 256 + tid;
            int t  = id >> 9;
            int r  = (id >> 2) & 127;
            int sg = id & 3;
            const __nv_bfloat16* basep = (t == 0 ? Ahi : t == 1 ? Alo : t == 2 ? Whi : Wlo);
            int grow = (t < 2 ? bm : bn) + r;
            const __nv_bfloat16* src = basep + (size_t)grow * K + c * 32 + sg * 8;
            uint32_t dst = sbase + st * G_STG + t * G_TILE_B + r * 80 + sg * 16;
            asm volatile("cp.async.cg.shared.global [%0], [%1], 16;" :: "r"(dst), "l"(src));
        }
        asm volatile("cp.async.commit_group;" ::: "memory");
    };

    load(0, 0);

    for (int c = 0; c < nch; c++) {
        if (c + 1 < nch) {
            load(c + 1, (c + 1) & 1);
            asm volatile("cp.async.wait_group 1;" ::: "memory");
        } else {
            asm volatile("cp.async.wait_group 0;" ::: "memory");
        }
        __syncthreads();

        const uint32_t stb = sbase + (c & 1) * G_STG;
        const uint32_t aB[2] = { stb, stb + G_TILE_B };
        const uint32_t wB[2] = { stb + 2 * G_TILE_B, stb + 3 * G_TILE_B };
        const int arow = wr * 32 + (lane & 15);
        const int wrow = wc * 64 + (lane & 15);
        const int cc   = (lane >> 4) * 16;

#pragma unroll
        for (int ks = 0; ks < 2; ks++) {
            uint32_t afr[2][2][4];
#pragma unroll
            for (int s = 0; s < 2; s++)
#pragma unroll
                for (int mi = 0; mi < 2; mi++) {
                    uint32_t ad = aB[s] + (uint32_t)(arow + mi * 16) * 80 + ks * 32 + cc;
                    LDSM4(afr[s][mi], ad);
                }
#pragma unroll
            for (int wsp = 0; wsp < 2; wsp++) {
#pragma unroll
                for (int nb = 0; nb < 4; nb++) {
                    uint32_t r0, r1, r2, r3;
                    uint32_t bd = wB[wsp] + (uint32_t)(wrow + nb * 16) * 80 + ks * 32 + cc;
                    LDSM4B(r0, r1, r2, r3, bd);
#pragma unroll
                    for (int mi = 0; mi < 2; mi++) {
                        MMA4(acc[mi][nb * 2],     afr[0][mi], r0, r2);
                        MMA4(acc[mi][nb * 2 + 1], afr[0][mi], r1, r3);
                        if (wsp == 0) {
                            MMA4(acc[mi][nb * 2],     afr[1][mi], r0, r2);
                            MMA4(acc[mi][nb * 2 + 1], afr[1][mi], r1, r3);
                        }
                    }
                }
            }
        }
        __syncthreads();
    }

#pragma unroll
    for (int mi = 0; mi < 2; mi++) {
#pragma unroll
        for (int ni = 0; ni < 8; ni++) {
            int r0 = bm + wr * 32 + mi * 16 + (lane >> 2);
            int c0 = bn + wc * 64 + ni * 8 + (lane & 3) * 2;
            float b0v = bias[c0], b1v = bias[c0 + 1];
            float2 v0 = { acc[mi][ni][0] + b0v, acc[mi][ni][1] + b1v };
            float2 v1 = { acc[mi][ni][2] + b0v, acc[mi][ni][3] + b1v };
            *(float2*)&C[(size_t)r0 * N + c0]       = v0;
            *(float2*)&C[(size_t)(r0 + 8) * N + c0] = v1;
        }
    }
}

// fp32 -> bf16 hi/lo split
__global__ void split_bf16(const float* __restrict__ s, __nv_bfloat16* __restrict__ hi,
                           __nv_bfloat16* __restrict__ lo, long n)
{
    long stride = (long)gridDim.x * blockDim.x;
    for (long i = blockIdx.x * (long)blockDim.x + threadIdx.x; i < n; i += stride) {
        float v = s[i];
        __nv_bfloat16 h = __float2bfloat16(v);
        hi[i] = h;
        lo[i] = __float2bfloat16(v - __bfloat162float(h));
    }
}

// =====================  HMMA recurrent cell machinery ========================
// Block tile M=128 (batch) x N=32 (4 gates x 8 units); 8 warps of 16x32.
// K chunks of 64 (was 32), 2-stage cp.async.
// Stage: Ah|Al (128 rows x 144B) + Wh|Wl (32 rows x 144B). 144B stride keeps
// ldmatrix conflict-free (36 words -> 4-bank shift per row covers 32 banks).

#define RC_ATILE 18432                 // 128*144
#define RC_WOFF  36864                 // 2*RC_ATILE
#define RC_WTILE 4608                  // 32*144
#define RC_STG   46080                 // RC_WOFF + 2*RC_WTILE
#define RC_GS_OFF (2 * RC_STG)         // 92160
#define RC_DSM   (RC_GS_OFF + 128 * 34 * 4)   // 109568

struct Seg {
    const __nv_bfloat16 *Ah, *Al, *Wh, *Wl;
    int lda, ldw, nch;   // nch in 64-wide chunks
};

__device__ __forceinline__ void rc_load64(const Seg& s, int kc, uint32_t stb,
                                          int tid, int ubase, int GST)
{
#pragma unroll
    for (int q = 0; q < 10; q++) {
        int id = q * 256 + tid;      // 0..2559
        uint32_t dst; const __nv_bfloat16* src;
        if (id < 2048) {             // A: 2 tiles x 128 rows x 8 segs
            int t = id >> 10, r = (id >> 3) & 127, sg = id & 7;
            src = (t ? s.Al : s.Ah) + (size_t)r * s.lda + kc + sg * 8;
            dst = stb + t * RC_ATILE + r * 144 + sg * 16;
        } else {                     // W: 2 tiles x 32 rows x 8 segs
            int id2 = id - 2048;     // 0..511
            int t = id2 >> 8, r = (id2 >> 3) & 31, sg = id2 & 7;
            int grow = (r >> 3) * GST + ubase + (r & 7);
            src = (t ? s.Wl : s.Wh) + (size_t)grow * s.ldw + kc + sg * 8;
            dst = stb + RC_WOFF + t * RC_WTILE + r * 144 + sg * 16;
        }
        asm volatile("cp.async.cg.shared.global [%0], [%1], 16;" :: "r"(dst), "l"(src));
    }
    asm volatile("cp.async.commit_group;" ::: "memory");
}

__device__ __forceinline__ void rc_consume64(uint32_t stb, int wid, int lane,
                                             float (*acc)[4])
{
    const uint32_t cc   = (lane >> 4) * 16;
    const uint32_t arow = wid * 16 + (lane & 15);
    const uint32_t wrow = (lane & 15);
#pragma unroll
    for (int ks = 0; ks < 4; ks++) {
        uint32_t ah[4], al[4];
        LDSM4(ah, stb + arow * 144 + ks * 32 + cc);
        LDSM4(al, stb + RC_ATILE + arow * 144 + ks * 32 + cc);
        uint32_t b0,b1,b2,b3,b4,b5,b6,b7;
        LDSM4B(b0,b1,b2,b3, stb + RC_WOFF + wrow * 144 + ks * 32 + cc);
        LDSM4B(b4,b5,b6,b7, stb + RC_WOFF + (wrow + 16) * 144 + ks * 32 + cc);
        uint32_t l0,l1,l2,l3,l4,l5,l6,l7;
        LDSM4B(l0,l1,l2,l3, stb + RC_WOFF + RC_WTILE + wrow * 144 + ks * 32 + cc);
        LDSM4B(l4,l5,l6,l7, stb + RC_WOFF + RC_WTILE + (wrow + 16) * 144 + ks * 32 + cc);
        MMA4(acc[0], ah, b0, b2); MMA4(acc[0], al, b0, b2); MMA4(acc[0], ah, l0, l2);
        MMA4(acc[1], ah, b1, b3); MMA4(acc[1], al, b1, b3); MMA4(acc[1], ah, l1, l3);
        MMA4(acc[2], ah, b4, b6); MMA4(acc[2], al, b4, b6); MMA4(acc[2], ah, l4, l6);
        MMA4(acc[3], ah, b5, b7); MMA4(acc[3], al, b5, b7); MMA4(acc[3], ah, l5, l7);
    }
}

__device__ __forceinline__ void rc_epilogue_to_smem(float (*gs)[34], float (*acc)[4],
                                                    int wid, int lane)
{
#pragma unroll
    for (int nt = 0; nt < 4; nt++) {
        int r0 = wid * 16 + (lane >> 2);
        int c0 = nt * 8 + (lane & 3) * 2;
        gs[r0][c0]     = acc[nt][0];
        gs[r0][c0 + 1] = acc[nt][1];
        gs[r0 + 8][c0]     = acc[nt][2];
        gs[r0 + 8][c0 + 1] = acc[nt][3];
    }
}

// ---------------- encoder recurrent step (HMMA) -------------------------------
__global__ __launch_bounds__(256) void enc_step_mma(
    const __nv_bfloat16* __restrict__ hh, const __nv_bfloat16* __restrict__ hl, // [dir][B][512]
    const __nv_bfloat16* __restrict__ Wh, const __nv_bfloat16* __restrict__ Wl, // [dir][2048][512]
    const float* __restrict__ xg, float* __restrict__ cst,
    __nv_bfloat16* __restrict__ hho, __nv_bfloat16* __restrict__ hlo,
    float* __restrict__ hs, int t)
{
    extern __shared__ char dsm[];
    const int tid = threadIdx.x, lane = tid & 31, wid = tid >> 5;
    const int dir = blockIdx.y, ubase = blockIdx.x * 8;
    const int td = dir ? (SS - 1 - t) : t;
    const uint32_t sb = smem_u32(dsm);
    float (*gs)[34] = (float (*)[34])(dsm + RC_GS_OFF);

    Seg s = { hh + (size_t)dir * BHV, hl + (size_t)dir * BHV,
              Wh + (size_t)dir * GEV * HH, Wl + (size_t)dir * GEV * HH,
              HH, HH, 8 };

    float acc[4][4];
#pragma unroll
    for (int nt = 0; nt < 4; nt++)
#pragma unroll
        for (int q = 0; q < 4; q++) acc[nt][q] = 0.0f;

    rc_load64(s, 0, sb, tid, ubase, HH);
    for (int ci = 0; ci < 8; ci++) {
        if (ci + 1 < 8) {
            rc_load64(s, (ci + 1) * 64, sb + ((ci + 1) & 1) * RC_STG, tid, ubase, HH);
            asm volatile("cp.async.wait_group 1;" ::: "memory");
        } else {
            asm volatile("cp.async.wait_group 0;" ::: "memory");
        }
        __syncthreads();
        rc_consume64(sb + (ci & 1) * RC_STG, wid, lane, acc);
        __syncthreads();
    }

    rc_epilogue_to_smem(gs, acc, wid, lane);
    __syncthreads();

    const float* xgp = xg + (size_t)dir * BSV * GEV;
    float* cp = cst + (size_t)dir * BHV;
#pragma unroll
    for (int k = 0; k < 4; k++) {
        int idx = k * 256 + tid;
        int b = idx >> 3, u = idx & 7;
        int uu = ubase + u;
        size_t xrow = ((size_t)b * SS + td) * GEV;
        float gi = gs[b][u]      + xgp[xrow + uu];
        float gf = gs[b][8 + u]  + xgp[xrow + 512 + uu];
        float gg = gs[b][16 + u] + xgp[xrow + 1024 + uu];
        float go = gs[b][24 + u] + xgp[xrow + 1536 + uu];
        int hidx = b * HH + uu;
        float c = sigf(gf) * cp[hidx] + sigf(gi) * tanhf(gg);
        float h = sigf(go) * tanhf(c);
        cp[hidx] = c;
        hs[((size_t)b * SS + td) * H2V + dir * HH + uu] = h;
        __nv_bfloat16 hb = __float2bfloat16(h);
        hho[(size_t)dir * BHV + hidx] = hb;
        hlo[(size_t)dir * BHV + hidx] = __float2bfloat16(h - __bfloat162float(hb));
    }
}

// ---------------- decoder cell (HMMA) -----------------------------------------
__global__ __launch_bounds__(256) void dec_cell_mma(
    const __nv_bfloat16* __restrict__ ch, const __nv_bfloat16* __restrict__ cl,  // ctx [B][1024]
    const __nv_bfloat16* __restrict__ ih, const __nv_bfloat16* __restrict__ il, int KB,
    const __nv_bfloat16* __restrict__ hh, const __nv_bfloat16* __restrict__ hl,  // h prev [B][1024]
    const __nv_bfloat16* __restrict__ Wih_h, const __nv_bfloat16* __restrict__ Wih_l, // ldw=H2V+KB
    const __nv_bfloat16* __restrict__ Whh_h, const __nv_bfloat16* __restrict__ Whh_l, // ldw=H2V
    const float* __restrict__ bias, float* __restrict__ cst,
    float* __restrict__ hfo, __nv_bfloat16* __restrict__ hho, __nv_bfloat16* __restrict__ hlo)
{
    extern __shared__ char dsm[];
    const int tid = threadIdx.x, lane = tid & 31, wid = tid >> 5;
    const int ubase = blockIdx.x * 8;
    const uint32_t sb = smem_u32(dsm);
    float (*gs)[34] = (float (*)[34])(dsm + RC_GS_OFF);
    const int ldih = H2V + KB;

    Seg segs[3] = {
        { ch, cl, Wih_h,       Wih_l,       H2V, ldih, 16 },
        { ih, il, Wih_h + H2V, Wih_l + H2V, KB,  ldih, KB >> 6 },
        { hh, hl, Whh_h,       Whh_l,       H2V, H2V,  16 }
    };
    const int total = 32 + (KB >> 6);

    float acc[4][4];
#pragma unroll
    for (int nt = 0; nt < 4; nt++)
#pragma unroll
        for (int q = 0; q < 4; q++) acc[nt][q] = 0.0f;

    int si = 0, kc = 0;
    rc_load64(segs[0], 0, sb, tid, ubase, H2V);
    for (int ci = 0; ci < total; ci++) {
        int nsi = si, nkc = kc + 64;
        if (nkc >= segs[nsi].nch * 64) { nsi++; nkc = 0; }
        if (ci + 1 < total) {
            rc_load64(segs[nsi], nkc, sb + ((ci + 1) & 1) * RC_STG, tid, ubase, H2V);
            asm volatile("cp.async.wait_group 1;" ::: "memory");
        } else {
            asm volatile("cp.async.wait_group 0;" ::: "memory");
        }
        __syncthreads();
        rc_consume64(sb + (ci & 1) * RC_STG, wid, lane, acc);
        __syncthreads();
        si = nsi; kc = nkc;
    }

    rc_epilogue_to_smem(gs, acc, wid, lane);
    __syncthreads();

#pragma unroll
    for (int k = 0; k < 4; k++) {
        int idx = k * 256 + tid;
        int b = idx >> 3, u = idx & 7;
        int uu = ubase + u;
        float gi = gs[b][u]      + bias[uu];
        float gf = gs[b][8 + u]  + bias[1024 + uu];
        float gg = gs[b][16 + u] + bias[2048 + uu];
        float go = gs[b][24 + u] + bias[3072 + uu];
        int hidx = b * H2V + uu;
        float c = sigf(gf) * cst[hidx] + sigf(gi) * tanhf(gg);
        float h = sigf(go) * tanhf(c);
        cst[hidx] = c;
        hfo[hidx] = h;
        __nv_bfloat16 hb = __float2bfloat16(h);
        hho[hidx] = hb;
        hlo[hidx] = __float2bfloat16(h - __bfloat162float(hb));
    }
}

// ---------------- fused 3-head attention (coalesced score pass) ---------------
__global__ __launch_bounds__(256) void attendF(
    const float* __restrict__ dh,      // parity base; head i at dh + i*2*BH2
    const float* __restrict__ keys,    // [head][B][S][H2]
    const float* __restrict__ enc,     // [B][S][H2]
    __nv_bfloat16* __restrict__ cxh, __nv_bfloat16* __restrict__ cxl)  // [head][B][H2]
{
    const int b = blockIdx.x, tid = threadIdx.x, lane = tid & 31, wid = tid >> 5;
    __shared__ float sh[3][H2V];
    __shared__ float sa[3][SS];
    __shared__ float redm[3][8];
    __shared__ float reds[3][8];

#pragma unroll
    for (int hd = 0; hd < 3; hd++)
        *(float4*)&sh[hd][tid * 4] =
            *(const float4*)&dh[(size_t)hd * 2 * BH2 + (size_t)b * H2V + tid * 4];
    __syncthreads();

    // score pass: warp-per-row, coalesced key reads; h held in registers
#pragma unroll
    for (int hd = 0; hd < 3; hd++) {
        float4 hr[8];
#pragma unroll
        for (int k = 0; k < 8; k++)
            hr[k] = *(const float4*)&sh[hd][k * 128 + lane * 4];
        const float* kb = keys + ((size_t)hd * BSV + (size_t)b * SS) * H2V;
        for (int s = wid * 32; s < wid * 32 + 32; s++) {
            const float* kr = kb + (size_t)s * H2V + lane * 4;
            float acc = 0.0f;
#pragma unroll
            for (int k = 0; k < 8; k++) {
                float4 kv = *(const float4*)(kr + k * 128);
                acc += kv.x * hr[k].x + kv.y * hr[k].y + kv.z * hr[k].z + kv.w * hr[k].w;
            }
#pragma unroll
            for (int off = 16; off; off >>= 1)
                acc += __shfl_xor_sync(0xffffffffu, acc, off);
            if (lane == 0) sa[hd][s] = acc;
        }
    }
    __syncthreads();

    // softmax over s (thread tid owns s=tid per head)
    float ev[3];
#pragma unroll
    for (int hd = 0; hd < 3; hd++) {
        float m = sa[hd][tid];
#pragma unroll
        for (int off = 16; off; off >>= 1)
            m = fmaxf(m, __shfl_xor_sync(0xffffffffu, m, off));
        if (lane == 0) redm[hd][wid] = m;
    }
    __syncthreads();
#pragma unroll
    for (int hd = 0; hd < 3; hd++) {
        float m = redm[hd][0];
#pragma unroll
        for (int i = 1; i < 8; i++) m = fmaxf(m, redm[hd][i]);
        float e = expf(sa[hd][tid] - m);
        ev[hd] = e;
        float ssum = e;
#pragma unroll
        for (int off = 16; off; off >>= 1)
            ssum += __shfl_xor_sync(0xffffffffu, ssum, off);
        if (lane == 0) reds[hd][wid] = ssum;
    }
    __syncthreads();
#pragma unroll
    for (int hd = 0; hd < 3; hd++) {
        float tot = reds[hd][0];
#pragma unroll
        for (int i = 1; i < 8; i++) tot += reds[hd][i];
        sa[hd][tid] = ev[hd] / tot;
    }
    __syncthreads();

    // weighted sum pass (already coalesced)
    float4 a0 = {0,0,0,0}, a1 = {0,0,0,0}, a2 = {0,0,0,0};
    const float* er = enc + (size_t)b * SS * H2V + tid * 4;
#pragma unroll 4
    for (int s = 0; s < SS; s++) {
        float4 ev4 = *(const float4*)(er + (size_t)s * H2V);
        float w0 = sa[0][s], w1 = sa[1][s], w2 = sa[2][s];
        a0.x += w0 * ev4.x; a0.y += w0 * ev4.y; a0.z += w0 * ev4.z; a0.w += w0 * ev4.w;
        a1.x += w1 * ev4.x; a1.y += w1 * ev4.y; a1.z += w1 * ev4.z; a1.w += w1 * ev4.w;
        a2.x += w2 * ev4.x; a2.y += w2 * ev4.y; a2.z += w2 * ev4.z; a2.w += w2 * ev4.w;
    }
#pragma unroll
    for (int hd = 0; hd < 3; hd++) {
        float4 v = hd == 0 ? a0 : hd == 1 ? a1 : a2;
        size_t base = (size_t)hd * BH2 + (size_t)b * H2V + tid * 4;
        float vv[4] = { v.x, v.y, v.z, v.w };
#pragma unroll
        for (int q = 0; q < 4; q++) {
            __nv_bfloat16 hb = __float2bfloat16(vv[q]);
            cxh[base + q] = hb;
            cxl[base + q] = __float2bfloat16(vv[q] - __bfloat162float(hb));
        }
    }
}

// ---------------- output projection + feedback --------------------------------
__global__ __launch_bounds__(64) void out_proj(
    const float* __restrict__ h,
    const float* __restrict__ W,
    const float* __restrict__ bias,
    float* __restrict__ y,
    __nv_bfloat16* __restrict__ pvh, __nv_bfloat16* __restrict__ pvl,
    int t)
{
    const int b = blockIdx.x, d = threadIdx.x;
    __shared__ float sh[H2V];
    for (int i = d; i < H2V; i += 64) sh[i] = h[(size_t)b * H2V + i];
    __syncthreads();
    float acc = bias[d];
    const float* wr = W + (size_t)d * H2V;
    for (int k = 0; k < H2V; k += 4) {
        float4 wv = *(const float4*)(wr + k);
        acc += wv.x * sh[k] + wv.y * sh[k + 1] + wv.z * sh[k + 2] + wv.w * sh[k + 3];
    }
    y[((size_t)b * TT + t) * DD + d] = acc;
    __nv_bfloat16 hb = __float2bfloat16(acc);
    pvh[b * DD + d] = hb;
    pvl[b * DD + d] = __float2bfloat16(acc - __bfloat162float(hb));
}

__global__ void set_prev(const float* __restrict__ x,
                         __nv_bfloat16* __restrict__ pvh, __nv_bfloat16* __restrict__ pvl)
{
    int i = blockIdx.x * blockDim.x + threadIdx.x;
    if (i < BB * DD) {
        int b = i / DD, d = i % DD;
        float v = x[((size_t)b * SS + (SS - 1)) * DD + d];
        __nv_bfloat16 hb = __float2bfloat16(v);
        pvh[i] = hb;
        pvl[i] = __float2bfloat16(v - __bfloat162float(hb));
    }
}

// ---------------- host orchestration ------------------------------------------
extern "C" void kernel_launch(void* const* d_in, const int* in_sizes, int n_in,
                              void* d_out, int out_size)
{
    (void)in_sizes; (void)n_in; (void)out_size;
    const float* x        = (const float*)d_in[0];
    const float* enc0_Wih = (const float*)d_in[1];
    const float* enc0_Whh = (const float*)d_in[2];
    const float* enc0_b   = (const float*)d_in[3];
    const float* enc1_Wih = (const float*)d_in[4];
    const float* enc1_Whh = (const float*)d_in[5];
    const float* enc1_b   = (const float*)d_in[6];
    const float* attnW[3] = {(const float*)d_in[7],  (const float*)d_in[9],  (const float*)d_in[11]};
    const float* attnb[3] = {(const float*)d_in[8],  (const float*)d_in[10], (const float*)d_in[12]};
    const float* dec1_Wih = (const float*)d_in[13];
    const float* dec1_Whh = (const float*)d_in[14];
    const float* dec1_b   = (const float*)d_in[15];
    const float* dec2_Wih = (const float*)d_in[16];
    const float* dec2_Whh = (const float*)d_in[17];
    const float* dec2_b   = (const float*)d_in[18];
    const float* dec3_Wih = (const float*)d_in[19];
    const float* dec3_Whh = (const float*)d_in[20];
    const float* dec3_b   = (const float*)d_in[21];
    const float* out_W    = (const float*)d_in[22];
    const float* out_b    = (const float*)d_in[23];
    float* out = (float*)d_out;

    float *xg, *h0, *enc, *keys, *ec, *dh, *dcst;
    __nv_bfloat16 *ah, *al, *wh, *wl, *rwh, *rwl;
    __nv_bfloat16 *ehbh, *ehbl, *dhbh, *dhbl, *cxh, *cxl, *pvh, *pvl;
    cudaGetSymbolAddress((void**)&xg,   g_xg);
    cudaGetSymbolAddress((void**)&h0,   g_h0);
    cudaGetSymbolAddress((void**)&enc,  g_enc);
    cudaGetSymbolAddress((void**)&keys, g_keys);
    cudaGetSymbolAddress((void**)&ec,   g_ec);
    cudaGetSymbolAddress((void**)&dh,   g_dh);
    cudaGetSymbolAddress((void**)&dcst, g_dc);
    cudaGetSymbolAddress((void**)&ah,   g_abf_hi);
    cudaGetSymbolAddress((void**)&al,   g_abf_lo);
    cudaGetSymbolAddress((void**)&wh,   g_wbf_hi);
    cudaGetSymbolAddress((void**)&wl,   g_wbf_lo);
    cudaGetSymbolAddress((void**)&rwh,  g_rwh);
    cudaGetSymbolAddress((void**)&rwl,  g_rwl);
    cudaGetSymbolAddress((void**)&ehbh, g_ehbh);
    cudaGetSymbolAddress((void**)&ehbl, g_ehbl);
    cudaGetSymbolAddress((void**)&dhbh, g_dhbh);
    cudaGetSymbolAddress((void**)&dhbl, g_dhbl);
    cudaGetSymbolAddress((void**)&cxh,  g_cxh);
    cudaGetSymbolAddress((void**)&cxl,  g_cxl);
    cudaGetSymbolAddress((void**)&pvh,  g_pvh);
    cudaGetSymbolAddress((void**)&pvl,  g_pvl);

    cudaFuncSetAttribute(gemm_mma,     cudaFuncAttributeMaxDynamicSharedMemorySize, G_DSM);
    cudaFuncSetAttribute(enc_step_mma, cudaFuncAttributeMaxDynamicSharedMemorySize, RC_DSM);
    cudaFuncSetAttribute(dec_cell_mma, cudaFuncAttributeMaxDynamicSharedMemorySize, RC_DSM);

    const size_t dirXG = (size_t)BSV * GEV;

    // ---- pre-split recurrent weights (constant across steps) ----
    split_bf16<<<1024, 256>>>(enc0_Whh, rwh + OFF_E0,  rwl + OFF_E0,  2L * GEV * HH);
    split_bf16<<<1024, 256>>>(enc1_Whh, rwh + OFF_E1,  rwl + OFF_E1,  2L * GEV * HH);
    split_bf16<<<1024, 256>>>(dec1_Wih, rwh + OFF_D1I, rwl + OFF_D1I, (long)GDV * (H2V + DD));
    split_bf16<<<1024, 256>>>(dec2_Wih, rwh + OFF_D2I, rwl + OFF_D2I, (long)GDV * 2 * H2V);
    split_bf16<<<1024, 256>>>(dec3_Wih, rwh + OFF_D3I, rwl + OFF_D3I, (long)GDV * 2 * H2V);
    split_bf16<<<1024, 256>>>(dec1_Whh, rwh + OFF_D1H, rwl + OFF_D1H, (long)GDV * H2V);
    split_bf16<<<1024, 256>>>(dec2_Whh, rwh + OFF_D2H, rwl + OFF_D2H, (long)GDV * H2V);
    split_bf16<<<1024, 256>>>(dec3_Whh, rwh + OFF_D3H, rwl + OFF_D3H, (long)GDV * H2V);

    // ---- encoder layer 0 ----
    cudaMemsetAsync(ehbh, 0, sizeof(__nv_bfloat16) * 2 * 2 * BHV);
    cudaMemsetAsync(ehbl, 0, sizeof(__nv_bfloat16) * 2 * 2 * BHV);
    cudaMemsetAsync(ec,   0, sizeof(float) * 2 * BHV);
    split_bf16<<<1024, 256>>>(x, ah, al, (long)BSV * DD);
    split_bf16<<<1024, 256>>>(enc0_Wih, wh, wl, 2L * GEV * DD);
    gemm_mma<<<dim3(GEV / 128, BSV / 128), 256, G_DSM>>>(ah, al, wh, wl, enc0_b, xg, GEV, DD);
    gemm_mma<<<dim3(GEV / 128, BSV / 128), 256, G_DSM>>>(ah, al, wh + (size_t)GEV * DD, wl + (size_t)GEV * DD,
                                                         enc0_b + GEV, xg + dirXG, GEV, DD);
    const size_t eps = (size_t)2 * BHV;   // encoder parity stride (elems)
    for (int t = 0; t < SS; t++) {
        int par = t & 1;
        enc_step_mma<<<dim3(64, 2), 256, RC_DSM>>>(
            ehbh + par * eps, ehbl + par * eps,
            rwh + OFF_E0, rwl + OFF_E0,
            xg, ec,
            ehbh + (par ^ 1) * eps, ehbl + (par ^ 1) * eps,
            h0, t);
    }

    // ---- encoder layer 1 ----
    cudaMemsetAsync(ehbh, 0, sizeof(__nv_bfloat16) * 2 * 2 * BHV);
    cudaMemsetAsync(ehbl, 0, sizeof(__nv_bfloat16) * 2 * 2 * BHV);
    cudaMemsetAsync(ec,   0, sizeof(float) * 2 * BHV);
    split_bf16<<<1024, 256>>>(h0, ah, al, (long)BSV * H2V);
    split_bf16<<<1024, 256>>>(enc1_Wih, wh, wl, 2L * GEV * H2V);
    gemm_mma<<<dim3(GEV / 128, BSV / 128), 256, G_DSM>>>(ah, al, wh, wl, enc1_b, xg, GEV, H2V);
    gemm_mma<<<dim3(GEV / 128, BSV / 128), 256, G_DSM>>>(ah, al, wh + (size_t)GEV * H2V, wl + (size_t)GEV * H2V,
                                                         enc1_b + GEV, xg + dirXG, GEV, H2V);
    for (int t = 0; t < SS; t++) {
        int par = t & 1;
        enc_step_mma<<<dim3(64, 2), 256, RC_DSM>>>(
            ehbh + par * eps, ehbl + par * eps,
            rwh + OFF_E1, rwl + OFF_E1,
            xg, ec,
            ehbh + (par ^ 1) * eps, ehbl + (par ^ 1) * eps,
            enc, t);
    }

    // ---- keys ----
    split_bf16<<<1024, 256>>>(enc, ah, al, (long)BSV * H2V);
    for (int i = 0; i < 3; i++)
        split_bf16<<<1024, 256>>>(attnW[i], wh + (size_t)i * H2V * H2V, wl + (size_t)i * H2V * H2V,
                                  (long)H2V * H2V);
    for (int i = 0; i < 3; i++)
        gemm_mma<<<dim3(H2V / 128, BSV / 128), 256, G_DSM>>>(ah, al,
                                                             wh + (size_t)i * H2V * H2V,
                                                             wl + (size_t)i * H2V * H2V,
                                                             attnb[i], keys + (size_t)i * BSV * H2V,
                                                             H2V, H2V);

    // ---- decoder init ----
    cudaMemsetAsync(dh,   0, sizeof(float) * 6 * BH2);
    cudaMemsetAsync(dcst, 0, sizeof(float) * 3 * BH2);
    cudaMemsetAsync(dhbh, 0, sizeof(__nv_bfloat16) * 6 * BH2);
    cudaMemsetAsync(dhbl, 0, sizeof(__nv_bfloat16) * 6 * BH2);
    set_prev<<<32, 256>>>(x, pvh, pvl);

    // ---- decoder loop ----
    const size_t cs = (size_t)2 * BH2;   // per-cell stride (fp32 & bf16 mirrors)
    for (int t = 0; t < TT; t++) {
        int par = t & 1;
        attendF<<<BB, 256>>>(dh + (size_t)par * BH2, keys, enc, cxh, cxl);

        // cell 1: inB = prev y (KB=64)
        dec_cell_mma<<<128, 256, RC_DSM>>>(
            cxh, cxl, pvh, pvl, DD,
            dhbh + 0 * cs + (size_t)par * BH2, dhbl + 0 * cs + (size_t)par * BH2,
            rwh + OFF_D1I, rwl + OFF_D1I, rwh + OFF_D1H, rwl + OFF_D1H,
            dec1_b, dcst + 0 * BH2,
            dh + 0 * cs + (size_t)(par ^ 1) * BH2,
            dhbh + 0 * cs + (size_t)(par ^ 1) * BH2, dhbl + 0 * cs + (size_t)(par ^ 1) * BH2);

        // cell 2: inB = h1 (new)
        dec_cell_mma<<<128, 256, RC_DSM>>>(
            cxh + BH2, cxl + BH2,
            dhbh + 0 * cs + (size_t)(par ^ 1) * BH2, dhbl + 0 * cs + (size_t)(par ^ 1) * BH2, H2V,
            dhbh + 1 * cs + (size_t)par * BH2, dhbl + 1 * cs + (size_t)par * BH2,
            rwh + OFF_D2I, rwl + OFF_D2I, rwh + OFF_D2H, rwl + OFF_D2H,
            dec2_b, dcst + 1 * BH2,
            dh + 1 * cs + (size_t)(par ^ 1) * BH2,
            dhbh + 1 * cs + (size_t)(par ^ 1) * BH2, dhbl + 1 * cs + (size_t)(par ^ 1) * BH2);

        // cell 3: inB = h2 (new)
        dec_cell_mma<<<128, 256, RC_DSM>>>(
            cxh + 2 * BH2, cxl + 2 * BH2,
            dhbh + 1 * cs + (size_t)(par ^ 1) * BH2, dhbl + 1 * cs + (size_t)(par ^ 1) * BH2, H2V,
            dhbh + 2 * cs + (size_t)par * BH2, dhbl + 2 * cs + (size_t)par * BH2,
            rwh + OFF_D3I, rwl + OFF_D3I, rwh + OFF_D3H, rwl + OFF_D3H,
            dec3_b, dcst + 2 * BH2,
            dh + 2 * cs + (size_t)(par ^ 1) * BH2,
            dhbh + 2 * cs + (size_t)(par ^ 1) * BH2, dhbl + 2 * cs + (size_t)(par ^ 1) * BH2);

        out_proj<<<BB, 64>>>(dh + 2 * cs + (size_t)(par ^ 1) * BH2, out_W, out_b, out, pvh, pvl, t);
    }
}